// round 6
// baseline (speedup 1.0000x reference)
#include <cuda_runtime.h>
#include <stdint.h>
#include <math.h>

#define NROWS  14336
#define SEQL   512
#define DMODEL 512
#define NEXP   8
#define NHID   256
#define NVARS  7
#define CAP    NROWS
#define MAVG   25
#define PAD    12
#define NX     (NROWS * SEQL)
#define NW1    (NHID * SEQL)

// ---------------- scratch ----------------
__device__ float g_xn  [NROWS * SEQL];          // tf32-rounded normalized series
__device__ float g_h   [NROWS * NHID];
__device__ float g_weff[NEXP * DMODEL * SEQL];  // tf32-rounded folded weights
__device__ float g_xh  [NX];                    // hi split of raw x
__device__ float g_xl  [NX];                    // lo split of raw x
__device__ float g_w1h [NW1];
__device__ float g_w1l [NW1];
__device__ int   g_tkidx[NROWS * 2];
__device__ float g_tkg  [NROWS * 2];
__device__ int   g_cnt [NEXP];
__device__ float g_imp [NEXP];
__device__ float g_load[NEXP];
__device__ int   g_rows[NEXP * CAP];
__device__ float g_rowg[NEXP * CAP];

// ---------------- helpers ----------------
__device__ __forceinline__ void cp16(float* dst, const float* src) {
    uint32_t d = (uint32_t)__cvta_generic_to_shared(dst);
    asm volatile("cp.async.cg.shared.global [%0], [%1], 16;\n" :: "r"(d), "l"(src));
}
__device__ __forceinline__ void cp16z(float* dst, const float* src, int pred) {
    uint32_t d = (uint32_t)__cvta_generic_to_shared(dst);
    int bytes = pred ? 16 : 0;
    asm volatile("cp.async.cg.shared.global [%0], [%1], 16, %2;\n"
                 :: "r"(d), "l"(src), "r"(bytes));
}
#define CP_COMMIT() asm volatile("cp.async.commit_group;\n")
#define CP_WAIT0()  asm volatile("cp.async.wait_group 0;\n")
#define CP_WAIT1()  asm volatile("cp.async.wait_group 1;\n")
#define CP_WAIT2()  asm volatile("cp.async.wait_group 2;\n")

__device__ __forceinline__ float f2tf_f(float v) {
    uint32_t r; asm("cvt.rna.tf32.f32 %0, %1;" : "=r"(r) : "f"(v));
    return __uint_as_float(r);
}
__device__ __forceinline__ void mma8(float* c, const uint32_t* a, const uint32_t* b) {
    asm volatile(
        "mma.sync.aligned.m16n8k8.row.col.f32.tf32.tf32.f32 "
        "{%0,%1,%2,%3}, {%4,%5,%6,%7}, {%8,%9}, {%0,%1,%2,%3};"
        : "+f"(c[0]), "+f"(c[1]), "+f"(c[2]), "+f"(c[3])
        : "r"(a[0]), "r"(a[1]), "r"(a[2]), "r"(a[3]), "r"(b[0]), "r"(b[1]));
}

// ---------------- tiny init ----------------
__global__ void k_zero() {
    int t = threadIdx.x;
    if (t < NEXP) { g_cnt[t] = 0; g_imp[t] = 0.f; g_load[t] = 0.f; }
}

// ---------------- split x and gw1 into tf32 hi/lo planes ----------------
__global__ void __launch_bounds__(256) k_split(const float* __restrict__ x,
                                               const float* __restrict__ w1) {
    int i = blockIdx.x * 256 + threadIdx.x;   // float4 index
    const int nx4 = NX / 4;
    const int nw4 = NW1 / 4;
    if (i < nx4) {
        float4 v = ((const float4*)x)[i];
        float4 h, l;
        h.x = f2tf_f(v.x); l.x = f2tf_f(v.x - h.x);
        h.y = f2tf_f(v.y); l.y = f2tf_f(v.y - h.y);
        h.z = f2tf_f(v.z); l.z = f2tf_f(v.z - h.z);
        h.w = f2tf_f(v.w); l.w = f2tf_f(v.w - h.w);
        ((float4*)g_xh)[i] = h;
        ((float4*)g_xl)[i] = l;
    } else if (i < nx4 + nw4) {
        int j = i - nx4;
        float4 v = ((const float4*)w1)[j];
        float4 h, l;
        h.x = f2tf_f(v.x); l.x = f2tf_f(v.x - h.x);
        h.y = f2tf_f(v.y); l.y = f2tf_f(v.y - h.y);
        h.z = f2tf_f(v.z); l.z = f2tf_f(v.z - h.z);
        h.w = f2tf_f(v.w); l.w = f2tf_f(v.w - h.w);
        ((float4*)g_w1h)[j] = h;
        ((float4*)g_w1l)[j] = l;
    }
}

// ---------------- RevIN (writes tf32-rounded output) ----------------
__global__ void __launch_bounds__(128) k_revin(const float* __restrict__ x,
                                               const float* __restrict__ rw,
                                               const float* __restrict__ rb) {
    int n = blockIdx.x;
    int t = threadIdx.x;
    const float* xr = x + (size_t)n * SEQL;
    float v[4];
    float s = 0.f, ss = 0.f;
#pragma unroll
    for (int i = 0; i < 4; i++) {
        v[i] = xr[t + 128 * i];
        s += v[i]; ss += v[i] * v[i];
    }
#pragma unroll
    for (int o = 16; o; o >>= 1) {
        s  += __shfl_xor_sync(0xffffffffu, s, o);
        ss += __shfl_xor_sync(0xffffffffu, ss, o);
    }
    __shared__ float sh[2][4];
    int w = t >> 5;
    if ((t & 31) == 0) { sh[0][w] = s; sh[1][w] = ss; }
    __syncthreads();
    s  = sh[0][0] + sh[0][1] + sh[0][2] + sh[0][3];
    ss = sh[1][0] + sh[1][1] + sh[1][2] + sh[1][3];
    float mean = s * (1.f / SEQL);
    float var  = ss * (1.f / SEQL) - mean * mean;
    float sd   = sqrtf(var + 1e-5f);
    int vv = n % NVARS;
    float sc = rw[vv] / sd;
    float b  = rb[vv];
    float* o = g_xn + (size_t)n * SEQL;
#pragma unroll
    for (int i = 0; i < 4; i++) o[t + 128 * i] = f2tf_f((v[i] - mean) * sc + b);
}

// ---------------- Weff fold (writes tf32-rounded output) ----------------
__global__ void __launch_bounds__(128) k_weff(const float* __restrict__ Ws,
                                              const float* __restrict__ Wt) {
    int ep = blockIdx.x;
    const float* ws = Ws + (size_t)ep * SEQL;
    const float* wt = Wt + (size_t)ep * SEQL;
    __shared__ float sD[SEQL];
    __shared__ float sW[SEQL];
    int t = threadIdx.x;
    for (int i = t; i < SEQL; i += 128) {
        float a = ws[i];
        sW[i] = a;
        sD[i] = wt[i] - a;
    }
    __syncthreads();
    float* o = g_weff + (size_t)ep * SEQL;
    for (int j = t; j < SEQL; j += 128) {
        float g = 0.f;
        if (j == 0) {
            for (int l = 0; l <= PAD; l++) g += (float)(PAD + 1 - l) * sD[l];
        } else if (j == SEQL - 1) {
            for (int l = SEQL - 1 - PAD; l < SEQL; l++)
                g += (float)(l - (SEQL - 2 - PAD)) * sD[l];
        } else {
            int lo = j - PAD; if (lo < 0) lo = 0;
            int hi = j + PAD; if (hi > SEQL - 1) hi = SEQL - 1;
            for (int l = lo; l <= hi; l++) g += sD[l];
        }
        o[j] = f2tf_f(sW[j] + g * (1.f / MAVG));
    }
}

// ---------------- GEMM1 (3xTF32, pre-split operands): h = relu(x @ gw1^T) --
// K-chunk 8, 3-stage cp.async pipeline, 48KB smem, zero cvt in hot loop.
__global__ void __launch_bounds__(256, 2) k_gemm_h() {
    __shared__ float Ah[3][1024], Al[3][1024], Bh[3][1024], Bl[3][1024];
    int m0 = blockIdx.x * 128, n0 = blockIdx.y * 128;
    int t = threadIdx.x;
    int lane = t & 31, warp = t >> 5;
    int wm = warp >> 2, wn = warp & 3;
    int lr = lane >> 2, lc = lane & 3;
    int sw = lr & 4;                 // xor swizzle bit
    int kx0 = lc ^ sw;               // k index within chunk, first half
    int kx1 = (lc + 4) ^ sw;         // second half

    // per-thread cp.async assignment: 256 threads cover 128 rows x 2 chunks
    int lrow = t >> 1, lch = t & 1;
    int loff = lrow * 8 + ((lch * 4) ^ (lrow & 4));
    const float* pxh = g_xh + (size_t)(m0 + lrow) * SEQL + lch * 4;
    const float* pxl = g_xl + (size_t)(m0 + lrow) * SEQL + lch * 4;
    const float* pbh = g_w1h + (size_t)(n0 + lrow) * SEQL + lch * 4;
    const float* pbl = g_w1l + (size_t)(n0 + lrow) * SEQL + lch * 4;

    // loop-invariant fragment offsets
    int offB[4], offA[4];
#pragma unroll
    for (int ni = 0; ni < 4; ni++) offB[ni] = (wn * 32 + ni * 8 + lr) * 8;
#pragma unroll
    for (int mi = 0; mi < 4; mi++) offA[mi] = (wm * 64 + mi * 16 + lr) * 8;

    float acc[4][4][4];
#pragma unroll
    for (int i = 0; i < 4; i++)
#pragma unroll
        for (int j = 0; j < 4; j++)
#pragma unroll
            for (int q = 0; q < 4; q++) acc[i][j][q] = 0.f;

#define LOADH(buf, kt)                                   \
    {                                                    \
        cp16(&Ah[buf][loff], pxh + (kt) * 8);            \
        cp16(&Al[buf][loff], pxl + (kt) * 8);            \
        cp16(&Bh[buf][loff], pbh + (kt) * 8);            \
        cp16(&Bl[buf][loff], pbl + (kt) * 8);            \
    }

    LOADH(0, 0); CP_COMMIT();
    LOADH(1, 1); CP_COMMIT();

    const int KT = SEQL / 8;   // 64
    int cur = 0;
    for (int kt = 0; kt < KT; kt++) {
        if (kt + 2 < KT) {
            int nb = cur + 2; if (nb >= 3) nb -= 3;
            LOADH(nb, kt + 2);
            CP_COMMIT();
            CP_WAIT2();
        } else if (kt + 1 < KT) {
            CP_WAIT1();
        } else {
            CP_WAIT0();
        }
        __syncthreads();
        const float* ah_s = Ah[cur];
        const float* al_s = Al[cur];
        const float* bh_s = Bh[cur];
        const float* bl_s = Bl[cur];

        uint32_t bhf[4][2], blf[4][2];
#pragma unroll
        for (int ni = 0; ni < 4; ni++) {
            bhf[ni][0] = __float_as_uint(bh_s[offB[ni] + kx0]);
            bhf[ni][1] = __float_as_uint(bh_s[offB[ni] + kx1]);
            blf[ni][0] = __float_as_uint(bl_s[offB[ni] + kx0]);
            blf[ni][1] = __float_as_uint(bl_s[offB[ni] + kx1]);
        }
#pragma unroll
        for (int mi = 0; mi < 4; mi++) {
            uint32_t ahf[4], alf[4];
            ahf[0] = __float_as_uint(ah_s[offA[mi] + kx0]);
            ahf[1] = __float_as_uint(ah_s[offA[mi] + 64 + kx0]);
            ahf[2] = __float_as_uint(ah_s[offA[mi] + kx1]);
            ahf[3] = __float_as_uint(ah_s[offA[mi] + 64 + kx1]);
            alf[0] = __float_as_uint(al_s[offA[mi] + kx0]);
            alf[1] = __float_as_uint(al_s[offA[mi] + 64 + kx0]);
            alf[2] = __float_as_uint(al_s[offA[mi] + kx1]);
            alf[3] = __float_as_uint(al_s[offA[mi] + 64 + kx1]);
#pragma unroll
            for (int ni = 0; ni < 4; ni++) {
                mma8(acc[mi][ni], ahf, bhf[ni]);
                mma8(acc[mi][ni], alf, bhf[ni]);
                mma8(acc[mi][ni], ahf, blf[ni]);
            }
        }
        __syncthreads();
        cur++; if (cur >= 3) cur = 0;
    }
#undef LOADH

#pragma unroll
    for (int mi = 0; mi < 4; mi++) {
        int row = m0 + wm * 64 + mi * 16 + lr;
#pragma unroll
        for (int ni = 0; ni < 4; ni++) {
            int col = n0 + wn * 32 + ni * 8 + lc * 2;
            float2 v0 = make_float2(fmaxf(acc[mi][ni][0], 0.f), fmaxf(acc[mi][ni][1], 0.f));
            float2 v1 = make_float2(fmaxf(acc[mi][ni][2], 0.f), fmaxf(acc[mi][ni][3], 0.f));
            *(float2*)&g_h[(size_t)row * NHID + col]       = v0;
            *(float2*)&g_h[(size_t)(row + 8) * NHID + col] = v1;
        }
    }
}

// ---------------- gating head ----------------
__global__ void __launch_bounds__(256) k_gate(const float* __restrict__ gw2) {
    __shared__ float sg2[NEXP * NHID];
    int t = threadIdx.x;
    for (int i = t; i < NEXP * NHID; i += 256) sg2[i] = gw2[i];
    __syncthreads();
    int w = t >> 5, lane = t & 31;
    int r = blockIdx.x * 8 + w;
    const float* h = g_h + (size_t)r * NHID;
    float acc[NEXP] = {};
    for (int k = lane; k < NHID; k += 32) {
        float hv = h[k];
#pragma unroll
        for (int e = 0; e < NEXP; e++) acc[e] = fmaf(hv, sg2[e * NHID + k], acc[e]);
    }
#pragma unroll
    for (int e = 0; e < NEXP; e++)
#pragma unroll
        for (int o = 16; o; o >>= 1) acc[e] += __shfl_xor_sync(0xffffffffu, acc[e], o);
    if (lane == 0) {
        float mx = acc[0];
#pragma unroll
        for (int e = 1; e < NEXP; e++) mx = fmaxf(mx, acc[e]);
        float p[NEXP], sum = 0.f;
#pragma unroll
        for (int e = 0; e < NEXP; e++) { p[e] = expf(acc[e] - mx); sum += p[e]; }
        float inv = 1.f / sum;
#pragma unroll
        for (int e = 0; e < NEXP; e++) p[e] *= inv;
        int i1 = 0; float v1 = p[0];
#pragma unroll
        for (int e = 1; e < NEXP; e++) if (p[e] > v1) { v1 = p[e]; i1 = e; }
        int i2 = -1; float v2 = -1.f;
#pragma unroll
        for (int e = 0; e < NEXP; e++)
            if (e != i1 && p[e] > v2) { v2 = p[e]; i2 = e; }
        float den = v1 + v2 + 1e-6f;
        float g1 = v1 / den, g2 = v2 / den;
        g_tkidx[2 * r] = i1; g_tkidx[2 * r + 1] = i2;
        g_tkg[2 * r] = g1;   g_tkg[2 * r + 1] = g2;
        atomicAdd(&g_imp[i1], g1);
        atomicAdd(&g_imp[i2], g2);
        atomicAdd(&g_load[i1], 1.f);
        atomicAdd(&g_load[i2], 1.f);
    }
}

// ---------------- per-expert row lists ----------------
__global__ void __launch_bounds__(256) k_lists() {
    __shared__ int scnt[NEXP], sbase[NEXP];
    int t = threadIdx.x;
    if (t < NEXP) scnt[t] = 0;
    __syncthreads();
    int r = blockIdx.x * 256 + t;
    int i1 = g_tkidx[2 * r], i2 = g_tkidx[2 * r + 1];
    int l1 = atomicAdd(&scnt[i1], 1);
    int l2 = atomicAdd(&scnt[i2], 1);
    __syncthreads();
    if (t < NEXP) sbase[t] = atomicAdd(&g_cnt[t], scnt[t]);
    __syncthreads();
    int p1 = sbase[i1] + l1, p2 = sbase[i2] + l2;
    g_rows[i1 * CAP + p1] = r; g_rowg[i1 * CAP + p1] = g_tkg[2 * r];
    g_rows[i2 * CAP + p2] = r; g_rowg[i2 * CAP + p2] = g_tkg[2 * r + 1];
}

// ---------------- expert GEMM (tf32, pre-rounded operands) -----------------
__global__ void __launch_bounds__(256, 2) k_gemmE(float* __restrict__ y) {
    int e = blockIdx.z;
    int cnt = g_cnt[e];
    int m0 = blockIdx.x * 128;
    if (m0 >= cnt) return;
    __shared__ float As[2][128 * 16];
    __shared__ float Bs[2][128 * 16];
    __shared__ int   srow[128];
    __shared__ float sgt[128];
    int t = threadIdx.x;
    if (t < 128) {
        int m = m0 + t;
        srow[t] = (m < cnt) ? g_rows[e * CAP + m] : -1;
        sgt[t]  = (m < cnt) ? g_rowg[e * CAP + m] : 0.f;
    }
    __syncthreads();
    int n0 = blockIdx.y * 128;
    const float* B = g_weff + (size_t)e * DMODEL * SEQL;

    int lane = t & 31, warp = t >> 5;
    int wm = warp >> 2, wn = warp & 3;
    int lr = lane >> 2, lc = lane & 3;
    int sx = (lr & 6) << 1;

    float acc[4][4][4];
#pragma unroll
    for (int i = 0; i < 4; i++)
#pragma unroll
        for (int j = 0; j < 4; j++)
#pragma unroll
            for (int q = 0; q < 4; q++) acc[i][j][q] = 0.f;

#define LOADE(buf, kt)                                                         \
    {                                                                          \
        _Pragma("unroll")                                                      \
        for (int i = 0; i < 2; i++) {                                          \
            int c = i * 256 + t;                                               \
            int row = c >> 2, ch = c & 3;                                      \
            int off = row * 16 + ((ch * 4) ^ ((row & 6) << 1));                \
            int gr = srow[row];                                                \
            int grs = gr < 0 ? 0 : gr;                                         \
            cp16z(&As[buf][off], g_xn + (size_t)grs * SEQL + (kt) * 16 + ch * 4, gr >= 0); \
            cp16(&Bs[buf][off], B + (size_t)(n0 + row) * SEQL + (kt) * 16 + ch * 4); \
        }                                                                      \
    }

    LOADE(0, 0);
    CP_COMMIT();

    const int KT = SEQL / 16;
    for (int kt = 0; kt < KT; kt++) {
        int cur = kt & 1;
        if (kt + 1 < KT) {
            LOADE((kt + 1) & 1, kt + 1);
            CP_COMMIT();
            CP_WAIT1();
        } else {
            CP_WAIT0();
        }
        __syncthreads();
        const float* a_s = As[cur];
        const float* b_s = Bs[cur];
#pragma unroll
        for (int k8 = 0; k8 < 16; k8 += 8) {
            int k0 = (k8 + lc) ^ sx;
            int k1 = (k8 + lc + 4) ^ sx;
            uint32_t a[4][4], b[4][2];
#pragma unroll
            for (int mi = 0; mi < 4; mi++) {
                int mb = (wm * 64 + mi * 16 + lr) * 16;
                a[mi][0] = __float_as_uint(a_s[mb + k0]);
                a[mi][1] = __float_as_uint(a_s[mb + 128 + k0]);
                a[mi][2] = __float_as_uint(a_s[mb + k1]);
                a[mi][3] = __float_as_uint(a_s[mb + 128 + k1]);
            }
#pragma unroll
            for (int ni = 0; ni < 4; ni++) {
                int nb = (wn * 32 + ni * 8 + lr) * 16;
                b[ni][0] = __float_as_uint(b_s[nb + k0]);
                b[ni][1] = __float_as_uint(b_s[nb + k1]);
            }
#pragma unroll
            for (int mi = 0; mi < 4; mi++)
#pragma unroll
                for (int ni = 0; ni < 4; ni++)
                    mma8(acc[mi][ni], a[mi], b[ni]);
        }
        __syncthreads();
    }
#undef LOADE

#pragma unroll
    for (int mi = 0; mi < 4; mi++) {
        int ml = wm * 64 + mi * 16 + lr;
        int r0 = srow[ml], r1 = srow[ml + 8];
        float g0 = sgt[ml], g1 = sgt[ml + 8];
#pragma unroll
        for (int ni = 0; ni < 4; ni++) {
            int col = n0 + wn * 32 + ni * 8 + lc * 2;
            if (r0 >= 0) {
                atomicAdd(&y[(size_t)r0 * DMODEL + col],     g0 * acc[mi][ni][0]);
                atomicAdd(&y[(size_t)r0 * DMODEL + col + 1], g0 * acc[mi][ni][1]);
            }
            if (r1 >= 0) {
                atomicAdd(&y[(size_t)r1 * DMODEL + col],     g1 * acc[mi][ni][2]);
                atomicAdd(&y[(size_t)r1 * DMODEL + col + 1], g1 * acc[mi][ni][3]);
            }
        }
    }
}

// ---------------- loss ----------------
__global__ void k_loss(const void* lc, float* out, int out_size) {
    float mi = 0.f, ml = 0.f;
#pragma unroll
    for (int e = 0; e < NEXP; e++) { mi += g_imp[e]; ml += g_load[e]; }
    mi *= (1.f / NEXP); ml *= (1.f / NEXP);
    float vi = 0.f, vl = 0.f;
#pragma unroll
    for (int e = 0; e < NEXP; e++) {
        float di = g_imp[e] - mi;  vi += di * di;
        float dl = g_load[e] - ml; vl += dl * dl;
    }
    vi *= (1.f / (NEXP - 1)); vl *= (1.f / (NEXP - 1));
    float cvi = vi / (mi * mi + 1e-10f);
    float cvl = vl / (ml * ml + 1e-10f);
    float coef = 1.f;
    if (lc) {
        int ib = *(const int*)lc;
        float fb = __int_as_float(ib);
        float af = fabsf(fb);
        coef = (af >= 1e-6f && af <= 1e6f) ? fb : (float)ib;
    }
    out[out_size - 1] = (cvi + cvl) * coef;
}

// ---------------- launch ----------------
extern "C" void kernel_launch(void* const* d_in, const int* in_sizes, int n_in,
                              void* d_out, int out_size) {
    const float* x   = (const float*)d_in[0];
    const float* gw1 = (const float*)d_in[1];
    const float* gw2 = (const float*)d_in[2];
    const float* Ws  = (const float*)d_in[3];
    const float* Wt  = (const float*)d_in[4];
    const float* rw  = (const float*)d_in[5];
    const float* rb  = (const float*)d_in[6];
    const void*  lc  = (n_in >= 8) ? d_in[7] : (const void*)0;
    float* out = (float*)d_out;

    k_zero<<<1, 32>>>();
    cudaMemsetAsync(d_out, 0, (size_t)out_size * sizeof(float));
    k_split<<<(NX / 4 + NW1 / 4) / 256, 256>>>(x, gw1);
    k_revin<<<NROWS, 128>>>(x, rw, rb);
    k_weff<<<NEXP * DMODEL, 128>>>(Ws, Wt);
    k_gemm_h<<<dim3(NROWS / 128, NHID / 128), 256>>>();
    k_gate<<<NROWS / 8, 256>>>(gw2);
    k_lists<<<NROWS / 256, 256>>>();
    k_gemmE<<<dim3(CAP / 128, DMODEL / 128, NEXP), 256>>>(out);
    k_loss<<<1, 1>>>(lc, out, out_size);
}

// round 9
// speedup vs baseline: 1.4671x; 1.4671x over previous
#include <cuda_runtime.h>
#include <cuda_fp16.h>
#include <stdint.h>
#include <math.h>

#define NROWS  14336
#define SEQL   512
#define DMODEL 512
#define NEXP   8
#define NHID   256
#define NVARS  7
#define CAP    NROWS
#define MAVG   25
#define PAD    12
#define NX     (NROWS * SEQL)
#define NW1    (NHID * SEQL)

// ---------------- scratch ----------------
__device__ __half g_xnh [NX];                     // fp16 normalized series
__device__ float  g_h   [NROWS * NHID];
__device__ __half g_weffh[NEXP * DMODEL * SEQL];  // fp16 folded weights
__device__ __half g_xh  [NX];                     // hi split of raw x
__device__ __half g_xl  [NX];                     // lo split
__device__ __half g_w1h [NW1];
__device__ __half g_w1l [NW1];
__device__ int    g_tkidx[NROWS * 2];
__device__ float  g_tkg  [NROWS * 2];
__device__ int    g_cnt [NEXP];
__device__ float  g_imp [NEXP];
__device__ float  g_load[NEXP];
__device__ int    g_rows[NEXP * CAP];
__device__ float  g_rowg[NEXP * CAP];

// ---------------- helpers ----------------
__device__ __forceinline__ void cp16(void* dst, const void* src) {
    uint32_t d = (uint32_t)__cvta_generic_to_shared(dst);
    asm volatile("cp.async.cg.shared.global [%0], [%1], 16;\n" :: "r"(d), "l"(src));
}
__device__ __forceinline__ void cp16z(void* dst, const void* src, int pred) {
    uint32_t d = (uint32_t)__cvta_generic_to_shared(dst);
    int bytes = pred ? 16 : 0;
    asm volatile("cp.async.cg.shared.global [%0], [%1], 16, %2;\n"
                 :: "r"(d), "l"(src), "r"(bytes));
}
#define CP_COMMIT() asm volatile("cp.async.commit_group;\n")
#define CP_WAIT0()  asm volatile("cp.async.wait_group 0;\n")
#define CP_WAIT1()  asm volatile("cp.async.wait_group 1;\n")

// fp16 m16n8k16, f32 accumulate
__device__ __forceinline__ void mma16(float* c, const uint32_t* a, const uint32_t* b) {
    asm volatile(
        "mma.sync.aligned.m16n8k16.row.col.f32.f16.f16.f32 "
        "{%0,%1,%2,%3}, {%4,%5,%6,%7}, {%8,%9}, {%0,%1,%2,%3};"
        : "+f"(c[0]), "+f"(c[1]), "+f"(c[2]), "+f"(c[3])
        : "r"(a[0]), "r"(a[1]), "r"(a[2]), "r"(a[3]), "r"(b[0]), "r"(b[1]));
}

// ---------------- tiny init ----------------
__global__ void k_zero() {
    int t = threadIdx.x;
    if (t < NEXP) { g_cnt[t] = 0; g_imp[t] = 0.f; g_load[t] = 0.f; }
}

// ---------------- split x and gw1 into fp16 hi/lo planes ----------------
__global__ void __launch_bounds__(256) k_split(const float* __restrict__ x,
                                               const float* __restrict__ w1) {
    int i = blockIdx.x * 256 + threadIdx.x;   // float4 group index
    const int nx4 = NX / 4;
    const int nw4 = NW1 / 4;
    const float* src;
    __half *dh, *dl;
    int j;
    if (i < nx4)            { src = x;  dh = g_xh;  dl = g_xl;  j = i; }
    else if (i < nx4 + nw4) { src = w1; dh = g_w1h; dl = g_w1l; j = i - nx4; }
    else return;
    float4 v = ((const float4*)src)[j];
    __half h0 = __float2half_rn(v.x), h1 = __float2half_rn(v.y);
    __half h2 = __float2half_rn(v.z), h3 = __float2half_rn(v.w);
    __half l0 = __float2half_rn(v.x - __half2float(h0));
    __half l1 = __float2half_rn(v.y - __half2float(h1));
    __half l2 = __float2half_rn(v.z - __half2float(h2));
    __half l3 = __float2half_rn(v.w - __half2float(h3));
    ((__half2*)dh)[2 * j]     = __halves2half2(h0, h1);
    ((__half2*)dh)[2 * j + 1] = __halves2half2(h2, h3);
    ((__half2*)dl)[2 * j]     = __halves2half2(l0, l1);
    ((__half2*)dl)[2 * j + 1] = __halves2half2(l2, l3);
}

// ---------------- RevIN (fp16 output) ----------------
__global__ void __launch_bounds__(128) k_revin(const float* __restrict__ x,
                                               const float* __restrict__ rw,
                                               const float* __restrict__ rb) {
    int n = blockIdx.x;
    int t = threadIdx.x;
    const float* xr = x + (size_t)n * SEQL;
    float v[4];
    float s = 0.f, ss = 0.f;
#pragma unroll
    for (int i = 0; i < 4; i++) {
        v[i] = xr[t + 128 * i];
        s += v[i]; ss += v[i] * v[i];
    }
#pragma unroll
    for (int o = 16; o; o >>= 1) {
        s  += __shfl_xor_sync(0xffffffffu, s, o);
        ss += __shfl_xor_sync(0xffffffffu, ss, o);
    }
    __shared__ float sh[2][4];
    int w = t >> 5;
    if ((t & 31) == 0) { sh[0][w] = s; sh[1][w] = ss; }
    __syncthreads();
    s  = sh[0][0] + sh[0][1] + sh[0][2] + sh[0][3];
    ss = sh[1][0] + sh[1][1] + sh[1][2] + sh[1][3];
    float mean = s * (1.f / SEQL);
    float var  = ss * (1.f / SEQL) - mean * mean;
    float sd   = sqrtf(var + 1e-5f);
    int vv = n % NVARS;
    float sc = rw[vv] / sd;
    float b  = rb[vv];
    __half* o = g_xnh + (size_t)n * SEQL;
#pragma unroll
    for (int i = 0; i < 4; i++) o[t + 128 * i] = __float2half_rn((v[i] - mean) * sc + b);
}

// ---------------- Weff fold (fp16 output) ----------------
__global__ void __launch_bounds__(128) k_weff(const float* __restrict__ Ws,
                                              const float* __restrict__ Wt) {
    int ep = blockIdx.x;
    const float* ws = Ws + (size_t)ep * SEQL;
    const float* wt = Wt + (size_t)ep * SEQL;
    __shared__ float sD[SEQL];
    __shared__ float sW[SEQL];
    int t = threadIdx.x;
    for (int i = t; i < SEQL; i += 128) {
        float a = ws[i];
        sW[i] = a;
        sD[i] = wt[i] - a;
    }
    __syncthreads();
    __half* o = g_weffh + (size_t)ep * SEQL;
    for (int j = t; j < SEQL; j += 128) {
        float g = 0.f;
        if (j == 0) {
            for (int l = 0; l <= PAD; l++) g += (float)(PAD + 1 - l) * sD[l];
        } else if (j == SEQL - 1) {
            for (int l = SEQL - 1 - PAD; l < SEQL; l++)
                g += (float)(l - (SEQL - 2 - PAD)) * sD[l];
        } else {
            int lo = j - PAD; if (lo < 0) lo = 0;
            int hi = j + PAD; if (hi > SEQL - 1) hi = SEQL - 1;
            for (int l = lo; l <= hi; l++) g += sD[l];
        }
        o[j] = __float2half_rn(sW[j] + g * (1.f / MAVG));
    }
}

// ---------------- GEMM1 (3x fp16 split): h = relu(x @ gw1^T) ----------------
// K-chunk 16, double-buffered, hi/lo fp16 planes, 32KB smem.
__global__ void __launch_bounds__(256, 2) k_gemm_h() {
    __shared__ __half Ah[2][2048], Al[2][2048], Bh[2][2048], Bl[2][2048];
    int m0 = blockIdx.x * 128, n0 = blockIdx.y * 128;
    int t = threadIdx.x;
    int lane = t & 31, warp = t >> 5;
    int wm = warp >> 2, wn = warp & 3;
    int lr = lane >> 2, lc = lane & 3;
    int sw = (lr & 4) << 1;            // half-index swizzle
    int k0 = (2 * lc) ^ sw;
    int k1 = (2 * lc + 8) ^ sw;

    // loader: 256 threads = 128 rows x 2 16B-chunks; per plane one cp16
    int lrow = t >> 1, lch = t & 1;
    int loff = lrow * 16 + ((lch * 8) ^ ((lrow & 4) << 1));
    const __half* pah = g_xh  + (size_t)(m0 + lrow) * SEQL + lch * 8;
    const __half* pal = g_xl  + (size_t)(m0 + lrow) * SEQL + lch * 8;
    const __half* pbh = g_w1h + (size_t)(n0 + lrow) * SEQL + lch * 8;
    const __half* pbl = g_w1l + (size_t)(n0 + lrow) * SEQL + lch * 8;

    int offB[4], offA[4];
#pragma unroll
    for (int ni = 0; ni < 4; ni++) offB[ni] = (wn * 32 + ni * 8 + lr) * 16;
#pragma unroll
    for (int mi = 0; mi < 4; mi++) offA[mi] = (wm * 64 + mi * 16 + lr) * 16;

    float acc[4][4][4];
#pragma unroll
    for (int i = 0; i < 4; i++)
#pragma unroll
        for (int j = 0; j < 4; j++)
#pragma unroll
            for (int q = 0; q < 4; q++) acc[i][j][q] = 0.f;

#define LOADH(buf, kt)                              \
    {                                               \
        cp16(&Ah[buf][loff], pah + (kt) * 16);      \
        cp16(&Al[buf][loff], pal + (kt) * 16);      \
        cp16(&Bh[buf][loff], pbh + (kt) * 16);      \
        cp16(&Bl[buf][loff], pbl + (kt) * 16);      \
    }

    LOADH(0, 0); CP_COMMIT();

    const int KT = SEQL / 16;    // 32
    for (int kt = 0; kt < KT; kt++) {
        int cur = kt & 1;
        if (kt + 1 < KT) {
            LOADH((kt + 1) & 1, kt + 1);
            CP_COMMIT();
            CP_WAIT1();
        } else {
            CP_WAIT0();
        }
        __syncthreads();
        const __half* ah_s = Ah[cur];
        const __half* al_s = Al[cur];
        const __half* bh_s = Bh[cur];
        const __half* bl_s = Bl[cur];

        uint32_t bhf[4][2], blf[4][2];
#pragma unroll
        for (int ni = 0; ni < 4; ni++) {
            bhf[ni][0] = *(const uint32_t*)&bh_s[offB[ni] + k0];
            bhf[ni][1] = *(const uint32_t*)&bh_s[offB[ni] + k1];
            blf[ni][0] = *(const uint32_t*)&bl_s[offB[ni] + k0];
            blf[ni][1] = *(const uint32_t*)&bl_s[offB[ni] + k1];
        }
#pragma unroll
        for (int mi = 0; mi < 4; mi++) {
            uint32_t ahf[4], alf[4];
            ahf[0] = *(const uint32_t*)&ah_s[offA[mi] + k0];
            ahf[1] = *(const uint32_t*)&ah_s[offA[mi] + 128 + k0];
            ahf[2] = *(const uint32_t*)&ah_s[offA[mi] + k1];
            ahf[3] = *(const uint32_t*)&ah_s[offA[mi] + 128 + k1];
            alf[0] = *(const uint32_t*)&al_s[offA[mi] + k0];
            alf[1] = *(const uint32_t*)&al_s[offA[mi] + 128 + k0];
            alf[2] = *(const uint32_t*)&al_s[offA[mi] + k1];
            alf[3] = *(const uint32_t*)&al_s[offA[mi] + 128 + k1];
#pragma unroll
            for (int ni = 0; ni < 4; ni++) {
                mma16(acc[mi][ni], ahf, bhf[ni]);
                mma16(acc[mi][ni], alf, bhf[ni]);
                mma16(acc[mi][ni], ahf, blf[ni]);
            }
        }
        __syncthreads();
    }
#undef LOADH

#pragma unroll
    for (int mi = 0; mi < 4; mi++) {
        int row = m0 + wm * 64 + mi * 16 + lr;
#pragma unroll
        for (int ni = 0; ni < 4; ni++) {
            int col = n0 + wn * 32 + ni * 8 + lc * 2;
            float2 v0 = make_float2(fmaxf(acc[mi][ni][0], 0.f), fmaxf(acc[mi][ni][1], 0.f));
            float2 v1 = make_float2(fmaxf(acc[mi][ni][2], 0.f), fmaxf(acc[mi][ni][3], 0.f));
            *(float2*)&g_h[(size_t)row * NHID + col]       = v0;
            *(float2*)&g_h[(size_t)(row + 8) * NHID + col] = v1;
        }
    }
}

// ---------------- gating head ----------------
__global__ void __launch_bounds__(256) k_gate(const float* __restrict__ gw2) {
    __shared__ float sg2[NEXP * NHID];
    int t = threadIdx.x;
    for (int i = t; i < NEXP * NHID; i += 256) sg2[i] = gw2[i];
    __syncthreads();
    int w = t >> 5, lane = t & 31;
    int r = blockIdx.x * 8 + w;
    const float* h = g_h + (size_t)r * NHID;
    float acc[NEXP] = {};
    for (int k = lane; k < NHID; k += 32) {
        float hv = h[k];
#pragma unroll
        for (int e = 0; e < NEXP; e++) acc[e] = fmaf(hv, sg2[e * NHID + k], acc[e]);
    }
#pragma unroll
    for (int e = 0; e < NEXP; e++)
#pragma unroll
        for (int o = 16; o; o >>= 1) acc[e] += __shfl_xor_sync(0xffffffffu, acc[e], o);
    if (lane == 0) {
        float mx = acc[0];
#pragma unroll
        for (int e = 1; e < NEXP; e++) mx = fmaxf(mx, acc[e]);
        float p[NEXP], sum = 0.f;
#pragma unroll
        for (int e = 0; e < NEXP; e++) { p[e] = expf(acc[e] - mx); sum += p[e]; }
        float inv = 1.f / sum;
#pragma unroll
        for (int e = 0; e < NEXP; e++) p[e] *= inv;
        int i1 = 0; float v1 = p[0];
#pragma unroll
        for (int e = 1; e < NEXP; e++) if (p[e] > v1) { v1 = p[e]; i1 = e; }
        int i2 = -1; float v2 = -1.f;
#pragma unroll
        for (int e = 0; e < NEXP; e++)
            if (e != i1 && p[e] > v2) { v2 = p[e]; i2 = e; }
        float den = v1 + v2 + 1e-6f;
        float g1 = v1 / den, g2 = v2 / den;
        g_tkidx[2 * r] = i1; g_tkidx[2 * r + 1] = i2;
        g_tkg[2 * r] = g1;   g_tkg[2 * r + 1] = g2;
        atomicAdd(&g_imp[i1], g1);
        atomicAdd(&g_imp[i2], g2);
        atomicAdd(&g_load[i1], 1.f);
        atomicAdd(&g_load[i2], 1.f);
    }
}

// ---------------- per-expert row lists ----------------
__global__ void __launch_bounds__(256) k_lists() {
    __shared__ int scnt[NEXP], sbase[NEXP];
    int t = threadIdx.x;
    if (t < NEXP) scnt[t] = 0;
    __syncthreads();
    int r = blockIdx.x * 256 + t;
    int i1 = g_tkidx[2 * r], i2 = g_tkidx[2 * r + 1];
    int l1 = atomicAdd(&scnt[i1], 1);
    int l2 = atomicAdd(&scnt[i2], 1);
    __syncthreads();
    if (t < NEXP) sbase[t] = atomicAdd(&g_cnt[t], scnt[t]);
    __syncthreads();
    int p1 = sbase[i1] + l1, p2 = sbase[i2] + l2;
    g_rows[i1 * CAP + p1] = r; g_rowg[i1 * CAP + p1] = g_tkg[2 * r];
    g_rows[i2 * CAP + p2] = r; g_rowg[i2 * CAP + p2] = g_tkg[2 * r + 1];
}

// ---------------- expert GEMM (fp16): y += gate * (xn_rows @ Weff[e]^T) ----
// K-chunk 32 (two k16 steps), double-buffered, 33KB smem.
__global__ void __launch_bounds__(256, 2) k_gemmE(float* __restrict__ y) {
    int e = blockIdx.z;
    int cnt = g_cnt[e];
    int m0 = blockIdx.x * 128;
    if (m0 >= cnt) return;
    __shared__ __half As[2][4096];
    __shared__ __half Bs[2][4096];
    __shared__ int   srow[128];
    __shared__ float sgt[128];
    int t = threadIdx.x;
    if (t < 128) {
        int m = m0 + t;
        srow[t] = (m < cnt) ? g_rows[e * CAP + m] : -1;
        sgt[t]  = (m < cnt) ? g_rowg[e * CAP + m] : 0.f;
    }
    __syncthreads();
    int n0 = blockIdx.y * 128;
    const __half* B = g_weffh + (size_t)e * DMODEL * SEQL;

    int lane = t & 31, warp = t >> 5;
    int wm = warp >> 2, wn = warp & 3;
    int lr = lane >> 2, lc = lane & 3;
    int sw = (lr & 6) << 2;

    int offB[4], offA[4];
#pragma unroll
    for (int ni = 0; ni < 4; ni++) offB[ni] = (wn * 32 + ni * 8 + lr) * 32;
#pragma unroll
    for (int mi = 0; mi < 4; mi++) offA[mi] = (wm * 64 + mi * 16 + lr) * 32;

    float acc[4][4][4];
#pragma unroll
    for (int i = 0; i < 4; i++)
#pragma unroll
        for (int j = 0; j < 4; j++)
#pragma unroll
            for (int q = 0; q < 4; q++) acc[i][j][q] = 0.f;

#define LOADE(buf, kt)                                                          \
    {                                                                           \
        _Pragma("unroll")                                                       \
        for (int i = 0; i < 2; i++) {                                           \
            int c = i * 256 + t;                                                \
            int row = c >> 2, ch = c & 3;                                       \
            int off = row * 32 + ((ch * 8) ^ ((row & 6) << 2));                 \
            int gr = srow[row];                                                 \
            int grs = gr < 0 ? 0 : gr;                                          \
            cp16z(&As[buf][off], g_xnh + (size_t)grs * SEQL + (kt) * 32 + ch * 8, gr >= 0); \
            cp16(&Bs[buf][off], B + (size_t)(n0 + row) * SEQL + (kt) * 32 + ch * 8); \
        }                                                                       \
    }

    LOADE(0, 0);
    CP_COMMIT();

    const int KT = SEQL / 32;   // 16
    for (int kt = 0; kt < KT; kt++) {
        int cur = kt & 1;
        if (kt + 1 < KT) {
            LOADE((kt + 1) & 1, kt + 1);
            CP_COMMIT();
            CP_WAIT1();
        } else {
            CP_WAIT0();
        }
        __syncthreads();
        const __half* a_s = As[cur];
        const __half* b_s = Bs[cur];
#pragma unroll
        for (int kb = 0; kb < 32; kb += 16) {
            int k0 = (kb + 2 * lc) ^ sw;
            int k1 = (kb + 2 * lc + 8) ^ sw;
            uint32_t a[4][4], b[4][2];
#pragma unroll
            for (int mi = 0; mi < 4; mi++) {
                a[mi][0] = *(const uint32_t*)&a_s[offA[mi] + k0];
                a[mi][1] = *(const uint32_t*)&a_s[offA[mi] + 256 + k0];
                a[mi][2] = *(const uint32_t*)&a_s[offA[mi] + k1];
                a[mi][3] = *(const uint32_t*)&a_s[offA[mi] + 256 + k1];
            }
#pragma unroll
            for (int ni = 0; ni < 4; ni++) {
                b[ni][0] = *(const uint32_t*)&b_s[offB[ni] + k0];
                b[ni][1] = *(const uint32_t*)&b_s[offB[ni] + k1];
            }
#pragma unroll
            for (int mi = 0; mi < 4; mi++)
#pragma unroll
                for (int ni = 0; ni < 4; ni++)
                    mma16(acc[mi][ni], a[mi], b[ni]);
        }
        __syncthreads();
    }
#undef LOADE

#pragma unroll
    for (int mi = 0; mi < 4; mi++) {
        int ml = wm * 64 + mi * 16 + lr;
        int r0 = srow[ml], r1 = srow[ml + 8];
        float g0 = sgt[ml], g1 = sgt[ml + 8];
#pragma unroll
        for (int ni = 0; ni < 4; ni++) {
            int col = n0 + wn * 32 + ni * 8 + lc * 2;
            if (r0 >= 0) {
                atomicAdd(&y[(size_t)r0 * DMODEL + col],     g0 * acc[mi][ni][0]);
                atomicAdd(&y[(size_t)r0 * DMODEL + col + 1], g0 * acc[mi][ni][1]);
            }
            if (r1 >= 0) {
                atomicAdd(&y[(size_t)r1 * DMODEL + col],     g1 * acc[mi][ni][2]);
                atomicAdd(&y[(size_t)r1 * DMODEL + col + 1], g1 * acc[mi][ni][3]);
            }
        }
    }
}

// ---------------- loss ----------------
__global__ void k_loss(const void* lc, float* out, int out_size) {
    float mi = 0.f, ml = 0.f;
#pragma unroll
    for (int e = 0; e < NEXP; e++) { mi += g_imp[e]; ml += g_load[e]; }
    mi *= (1.f / NEXP); ml *= (1.f / NEXP);
    float vi = 0.f, vl = 0.f;
#pragma unroll
    for (int e = 0; e < NEXP; e++) {
        float di = g_imp[e] - mi;  vi += di * di;
        float dl = g_load[e] - ml; vl += dl * dl;
    }
    vi *= (1.f / (NEXP - 1)); vl *= (1.f / (NEXP - 1));
    float cvi = vi / (mi * mi + 1e-10f);
    float cvl = vl / (ml * ml + 1e-10f);
    float coef = 1.f;
    if (lc) {
        int ib = *(const int*)lc;
        float fb = __int_as_float(ib);
        float af = fabsf(fb);
        coef = (af >= 1e-6f && af <= 1e6f) ? fb : (float)ib;
    }
    out[out_size - 1] = (cvi + cvl) * coef;
}

// ---------------- launch ----------------
extern "C" void kernel_launch(void* const* d_in, const int* in_sizes, int n_in,
                              void* d_out, int out_size) {
    const float* x   = (const float*)d_in[0];
    const float* gw1 = (const float*)d_in[1];
    const float* gw2 = (const float*)d_in[2];
    const float* Ws  = (const float*)d_in[3];
    const float* Wt  = (const float*)d_in[4];
    const float* rw  = (const float*)d_in[5];
    const float* rb  = (const float*)d_in[6];
    const void*  lc  = (n_in >= 8) ? d_in[7] : (const void*)0;
    float* out = (float*)d_out;

    k_zero<<<1, 32>>>();
    cudaMemsetAsync(d_out, 0, (size_t)out_size * sizeof(float));
    k_split<<<(NX / 4 + NW1 / 4 + 255) / 256, 256>>>(x, gw1);
    k_revin<<<NROWS, 128>>>(x, rw, rb);
    k_weff<<<NEXP * DMODEL, 128>>>(Ws, Wt);
    k_gemm_h<<<dim3(NROWS / 128, NHID / 128), 256>>>();
    k_gate<<<NROWS / 8, 256>>>(gw2);
    k_lists<<<NROWS / 256, 256>>>();
    k_gemmE<<<dim3(CAP / 128, DMODEL / 128, NEXP), 256>>>(out);
    k_loss<<<1, 1>>>(lc, out, out_size);
}

// round 10
// speedup vs baseline: 1.5523x; 1.0581x over previous
#include <cuda_runtime.h>
#include <cuda_fp16.h>
#include <stdint.h>
#include <math.h>

#define NROWS  14336
#define SEQL   512
#define DMODEL 512
#define NEXP   8
#define NHID   256
#define NVARS  7
#define CAP    NROWS
#define MAVG   25
#define PAD    12
#define NX     (NROWS * SEQL)
#define NW1    (NHID * SEQL)

// ---------------- scratch ----------------
__device__ __half g_xnh [NX];                     // fp16 normalized series
__device__ float  g_h   [NROWS * NHID];
__device__ __half g_weffh[NEXP * DMODEL * SEQL];  // fp16 folded weights
__device__ __half g_xh  [NX];                     // hi split of raw x
__device__ __half g_xl  [NX];                     // lo split
__device__ __half g_w1h [NW1];
__device__ __half g_w1l [NW1];
__device__ int    g_tkidx[NROWS * 2];
__device__ float  g_tkg  [NROWS * 2];
__device__ int    g_cnt [NEXP];
__device__ float  g_imp [NEXP];
__device__ float  g_load[NEXP];
__device__ int    g_rows[NEXP * CAP];
__device__ float  g_rowg[NEXP * CAP];

// ---------------- helpers ----------------
__device__ __forceinline__ void cp16(void* dst, const void* src) {
    uint32_t d = (uint32_t)__cvta_generic_to_shared(dst);
    asm volatile("cp.async.cg.shared.global [%0], [%1], 16;\n" :: "r"(d), "l"(src));
}
__device__ __forceinline__ void cp16z(void* dst, const void* src, int pred) {
    uint32_t d = (uint32_t)__cvta_generic_to_shared(dst);
    int bytes = pred ? 16 : 0;
    asm volatile("cp.async.cg.shared.global [%0], [%1], 16, %2;\n"
                 :: "r"(d), "l"(src), "r"(bytes));
}
#define CP_COMMIT() asm volatile("cp.async.commit_group;\n")
#define CP_WAIT0()  asm volatile("cp.async.wait_group 0;\n")
#define CP_WAIT1()  asm volatile("cp.async.wait_group 1;\n")

// fp16 m16n8k16, f32 accumulate
__device__ __forceinline__ void mma16(float* c, const uint32_t* a, const uint32_t* b) {
    asm volatile(
        "mma.sync.aligned.m16n8k16.row.col.f32.f16.f16.f32 "
        "{%0,%1,%2,%3}, {%4,%5,%6,%7}, {%8,%9}, {%0,%1,%2,%3};"
        : "+f"(c[0]), "+f"(c[1]), "+f"(c[2]), "+f"(c[3])
        : "r"(a[0]), "r"(a[1]), "r"(a[2]), "r"(a[3]), "r"(b[0]), "r"(b[1]));
}
__device__ __forceinline__ void redv2(float* ptr, float v0, float v1) {
    asm volatile("red.global.add.v2.f32 [%0], {%1, %2};"
                 :: "l"(ptr), "f"(v0), "f"(v1) : "memory");
}

// ---------------- tiny init ----------------
__global__ void k_zero() {
    int t = threadIdx.x;
    if (t < NEXP) { g_cnt[t] = 0; g_imp[t] = 0.f; g_load[t] = 0.f; }
}

// ---------------- split gw1 into fp16 hi/lo planes ----------------
__global__ void __launch_bounds__(256) k_splitw(const float* __restrict__ w1) {
    int j = blockIdx.x * 256 + threadIdx.x;   // float4 index, NW1/4 total
    float4 v = ((const float4*)w1)[j];
    __half h0 = __float2half_rn(v.x), h1 = __float2half_rn(v.y);
    __half h2 = __float2half_rn(v.z), h3 = __float2half_rn(v.w);
    __half l0 = __float2half_rn(v.x - __half2float(h0));
    __half l1 = __float2half_rn(v.y - __half2float(h1));
    __half l2 = __float2half_rn(v.z - __half2float(h2));
    __half l3 = __float2half_rn(v.w - __half2float(h3));
    ((__half2*)g_w1h)[2 * j]     = __halves2half2(h0, h1);
    ((__half2*)g_w1h)[2 * j + 1] = __halves2half2(h2, h3);
    ((__half2*)g_w1l)[2 * j]     = __halves2half2(l0, l1);
    ((__half2*)g_w1l)[2 * j + 1] = __halves2half2(l2, l3);
}

// ---------------- RevIN (fp16 out) + fused raw-x hi/lo split ----------------
__global__ void __launch_bounds__(128) k_revin(const float* __restrict__ x,
                                               const float* __restrict__ rw,
                                               const float* __restrict__ rb) {
    int n = blockIdx.x;
    int t = threadIdx.x;
    const float* xr = x + (size_t)n * SEQL;
    float v[4];
    float s = 0.f, ss = 0.f;
#pragma unroll
    for (int i = 0; i < 4; i++) {
        v[i] = xr[t + 128 * i];
        s += v[i]; ss += v[i] * v[i];
    }
#pragma unroll
    for (int o = 16; o; o >>= 1) {
        s  += __shfl_xor_sync(0xffffffffu, s, o);
        ss += __shfl_xor_sync(0xffffffffu, ss, o);
    }
    __shared__ float sh[2][4];
    int w = t >> 5;
    if ((t & 31) == 0) { sh[0][w] = s; sh[1][w] = ss; }
    __syncthreads();
    s  = sh[0][0] + sh[0][1] + sh[0][2] + sh[0][3];
    ss = sh[1][0] + sh[1][1] + sh[1][2] + sh[1][3];
    float mean = s * (1.f / SEQL);
    float var  = ss * (1.f / SEQL) - mean * mean;
    float sd   = sqrtf(var + 1e-5f);
    int vv = n % NVARS;
    float sc = rw[vv] / sd;
    float b  = rb[vv];
    size_t base = (size_t)n * SEQL;
#pragma unroll
    for (int i = 0; i < 4; i++) {
        int idx = t + 128 * i;
        g_xnh[base + idx] = __float2half_rn((v[i] - mean) * sc + b);
        __half hi = __float2half_rn(v[i]);
        g_xh[base + idx] = hi;
        g_xl[base + idx] = __float2half_rn(v[i] - __half2float(hi));
    }
}

// ---------------- Weff fold via inclusive scan (fp16 output) ----------------
__global__ void __launch_bounds__(128) k_weff(const float* __restrict__ Ws,
                                              const float* __restrict__ Wt) {
    int ep = blockIdx.x;
    __shared__ float sW[SEQL];
    __shared__ float sC[SEQL];     // inclusive cumsum of D = Wt - Ws
    __shared__ float wsum[4];
    int t = threadIdx.x;
    int lane = t & 31, w = t >> 5;

    float4 a = ((const float4*)(Ws + (size_t)ep * SEQL))[t];
    float4 b = ((const float4*)(Wt + (size_t)ep * SEQL))[t];
    float d0 = b.x - a.x, d1 = b.y - a.y, d2 = b.z - a.z, d3 = b.w - a.w;
    float c0 = d0, c1 = c0 + d1, c2 = c1 + d2, c3 = c2 + d3;
    // warp inclusive scan over per-thread sums (c3)
    float pre = c3;
#pragma unroll
    for (int o = 1; o < 32; o <<= 1) {
        float vv = __shfl_up_sync(0xffffffffu, pre, o);
        if (lane >= o) pre += vv;
    }
    if (lane == 31) wsum[w] = pre;
    __syncthreads();
    float base = 0.f;
#pragma unroll
    for (int ww = 0; ww < 4; ww++) if (ww < w) base += wsum[ww];
    float excl = base + pre - c3;
    int j4 = t * 4;
    sC[j4 + 0] = excl + c0;
    sC[j4 + 1] = excl + c1;
    sC[j4 + 2] = excl + c2;
    sC[j4 + 3] = excl + c3;
    sW[j4 + 0] = a.x; sW[j4 + 1] = a.y; sW[j4 + 2] = a.z; sW[j4 + 3] = a.w;
    __syncthreads();

    __half* o = g_weffh + (size_t)ep * SEQL;
#pragma unroll
    for (int i = 0; i < 4; i++) {
        int j = j4 + i;
        float g;
        if (j == 0) {
            g = 0.f;
            for (int k = 0; k <= PAD; k++) g += sC[k];
        } else if (j == SEQL - 1) {
            g = (float)(PAD + 1) * sC[SEQL - 1];
            for (int k = SEQL - 2 - PAD; k < SEQL - 1; k++) g -= sC[k];
        } else {
            int lo = j - PAD; if (lo < 0) lo = 0;
            int hi = j + PAD; if (hi > SEQL - 1) hi = SEQL - 1;
            g = sC[hi] - (lo > 0 ? sC[lo - 1] : 0.f);
        }
        o[j] = __float2half_rn(sW[j] + g * (1.f / MAVG));
    }
}

// ---------------- GEMM1 (3x fp16 split): h = relu(x @ gw1^T) ----------------
__global__ void __launch_bounds__(256, 2) k_gemm_h() {
    __shared__ __half Ah[2][2048], Al[2][2048], Bh[2][2048], Bl[2][2048];
    int m0 = blockIdx.x * 128, n0 = blockIdx.y * 128;
    int t = threadIdx.x;
    int lane = t & 31, warp = t >> 5;
    int wm = warp >> 2, wn = warp & 3;
    int lr = lane >> 2, lc = lane & 3;
    int sw = (lr & 4) << 1;
    int k0 = (2 * lc) ^ sw;
    int k1 = (2 * lc + 8) ^ sw;

    int lrow = t >> 1, lch = t & 1;
    int loff = lrow * 16 + ((lch * 8) ^ ((lrow & 4) << 1));
    const __half* pah = g_xh  + (size_t)(m0 + lrow) * SEQL + lch * 8;
    const __half* pal = g_xl  + (size_t)(m0 + lrow) * SEQL + lch * 8;
    const __half* pbh = g_w1h + (size_t)(n0 + lrow) * SEQL + lch * 8;
    const __half* pbl = g_w1l + (size_t)(n0 + lrow) * SEQL + lch * 8;

    int offB[4], offA[4];
#pragma unroll
    for (int ni = 0; ni < 4; ni++) offB[ni] = (wn * 32 + ni * 8 + lr) * 16;
#pragma unroll
    for (int mi = 0; mi < 4; mi++) offA[mi] = (wm * 64 + mi * 16 + lr) * 16;

    float acc[4][4][4];
#pragma unroll
    for (int i = 0; i < 4; i++)
#pragma unroll
        for (int j = 0; j < 4; j++)
#pragma unroll
            for (int q = 0; q < 4; q++) acc[i][j][q] = 0.f;

#define LOADH(buf, kt)                              \
    {                                               \
        cp16(&Ah[buf][loff], pah + (kt) * 16);      \
        cp16(&Al[buf][loff], pal + (kt) * 16);      \
        cp16(&Bh[buf][loff], pbh + (kt) * 16);      \
        cp16(&Bl[buf][loff], pbl + (kt) * 16);      \
    }

    LOADH(0, 0); CP_COMMIT();

    const int KT = SEQL / 16;    // 32
    for (int kt = 0; kt < KT; kt++) {
        int cur = kt & 1;
        if (kt + 1 < KT) {
            LOADH((kt + 1) & 1, kt + 1);
            CP_COMMIT();
            CP_WAIT1();
        } else {
            CP_WAIT0();
        }
        __syncthreads();
        const __half* ah_s = Ah[cur];
        const __half* al_s = Al[cur];
        const __half* bh_s = Bh[cur];
        const __half* bl_s = Bl[cur];

        uint32_t bhf[4][2], blf[4][2];
#pragma unroll
        for (int ni = 0; ni < 4; ni++) {
            bhf[ni][0] = *(const uint32_t*)&bh_s[offB[ni] + k0];
            bhf[ni][1] = *(const uint32_t*)&bh_s[offB[ni] + k1];
            blf[ni][0] = *(const uint32_t*)&bl_s[offB[ni] + k0];
            blf[ni][1] = *(const uint32_t*)&bl_s[offB[ni] + k1];
        }
#pragma unroll
        for (int mi = 0; mi < 4; mi++) {
            uint32_t ahf[4], alf[4];
            ahf[0] = *(const uint32_t*)&ah_s[offA[mi] + k0];
            ahf[1] = *(const uint32_t*)&ah_s[offA[mi] + 128 + k0];
            ahf[2] = *(const uint32_t*)&ah_s[offA[mi] + k1];
            ahf[3] = *(const uint32_t*)&ah_s[offA[mi] + 128 + k1];
            alf[0] = *(const uint32_t*)&al_s[offA[mi] + k0];
            alf[1] = *(const uint32_t*)&al_s[offA[mi] + 128 + k0];
            alf[2] = *(const uint32_t*)&al_s[offA[mi] + k1];
            alf[3] = *(const uint32_t*)&al_s[offA[mi] + 128 + k1];
#pragma unroll
            for (int ni = 0; ni < 4; ni++) {
                mma16(acc[mi][ni], ahf, bhf[ni]);
                mma16(acc[mi][ni], alf, bhf[ni]);
                mma16(acc[mi][ni], ahf, blf[ni]);
            }
        }
        __syncthreads();
    }
#undef LOADH

#pragma unroll
    for (int mi = 0; mi < 4; mi++) {
        int row = m0 + wm * 64 + mi * 16 + lr;
#pragma unroll
        for (int ni = 0; ni < 4; ni++) {
            int col = n0 + wn * 32 + ni * 8 + lc * 2;
            float2 v0 = make_float2(fmaxf(acc[mi][ni][0], 0.f), fmaxf(acc[mi][ni][1], 0.f));
            float2 v1 = make_float2(fmaxf(acc[mi][ni][2], 0.f), fmaxf(acc[mi][ni][3], 0.f));
            *(float2*)&g_h[(size_t)row * NHID + col]       = v0;
            *(float2*)&g_h[(size_t)(row + 8) * NHID + col] = v1;
        }
    }
}

// ---------------- gating head ----------------
__global__ void __launch_bounds__(256) k_gate(const float* __restrict__ gw2) {
    __shared__ float sg2[NEXP * NHID];
    int t = threadIdx.x;
    for (int i = t; i < NEXP * NHID; i += 256) sg2[i] = gw2[i];
    __syncthreads();
    int w = t >> 5, lane = t & 31;
    int r = blockIdx.x * 8 + w;
    const float* h = g_h + (size_t)r * NHID;
    float acc[NEXP] = {};
    for (int k = lane; k < NHID; k += 32) {
        float hv = h[k];
#pragma unroll
        for (int e = 0; e < NEXP; e++) acc[e] = fmaf(hv, sg2[e * NHID + k], acc[e]);
    }
#pragma unroll
    for (int e = 0; e < NEXP; e++)
#pragma unroll
        for (int o = 16; o; o >>= 1) acc[e] += __shfl_xor_sync(0xffffffffu, acc[e], o);
    if (lane == 0) {
        float mx = acc[0];
#pragma unroll
        for (int e = 1; e < NEXP; e++) mx = fmaxf(mx, acc[e]);
        float p[NEXP], sum = 0.f;
#pragma unroll
        for (int e = 0; e < NEXP; e++) { p[e] = expf(acc[e] - mx); sum += p[e]; }
        float inv = 1.f / sum;
#pragma unroll
        for (int e = 0; e < NEXP; e++) p[e] *= inv;
        int i1 = 0; float v1 = p[0];
#pragma unroll
        for (int e = 1; e < NEXP; e++) if (p[e] > v1) { v1 = p[e]; i1 = e; }
        int i2 = -1; float v2 = -1.f;
#pragma unroll
        for (int e = 0; e < NEXP; e++)
            if (e != i1 && p[e] > v2) { v2 = p[e]; i2 = e; }
        float den = v1 + v2 + 1e-6f;
        float g1 = v1 / den, g2 = v2 / den;
        g_tkidx[2 * r] = i1; g_tkidx[2 * r + 1] = i2;
        g_tkg[2 * r] = g1;   g_tkg[2 * r + 1] = g2;
        atomicAdd(&g_imp[i1], g1);
        atomicAdd(&g_imp[i2], g2);
        atomicAdd(&g_load[i1], 1.f);
        atomicAdd(&g_load[i2], 1.f);
    }
}

// ---------------- per-expert row lists ----------------
__global__ void __launch_bounds__(256) k_lists() {
    __shared__ int scnt[NEXP], sbase[NEXP];
    int t = threadIdx.x;
    if (t < NEXP) scnt[t] = 0;
    __syncthreads();
    int r = blockIdx.x * 256 + t;
    int i1 = g_tkidx[2 * r], i2 = g_tkidx[2 * r + 1];
    int l1 = atomicAdd(&scnt[i1], 1);
    int l2 = atomicAdd(&scnt[i2], 1);
    __syncthreads();
    if (t < NEXP) sbase[t] = atomicAdd(&g_cnt[t], scnt[t]);
    __syncthreads();
    int p1 = sbase[i1] + l1, p2 = sbase[i2] + l2;
    g_rows[i1 * CAP + p1] = r; g_rowg[i1 * CAP + p1] = g_tkg[2 * r];
    g_rows[i2 * CAP + p2] = r; g_rowg[i2 * CAP + p2] = g_tkg[2 * r + 1];
}

// ---------------- expert GEMM (fp16): y += gate * (xn_rows @ Weff[e]^T) ----
__global__ void __launch_bounds__(256, 2) k_gemmE(float* __restrict__ y) {
    int e = blockIdx.z;
    int cnt = g_cnt[e];
    int m0 = blockIdx.x * 128;
    if (m0 >= cnt) return;
    __shared__ __half As[2][4096];
    __shared__ __half Bs[2][4096];
    __shared__ int   srow[128];
    __shared__ float sgt[128];
    int t = threadIdx.x;
    if (t < 128) {
        int m = m0 + t;
        srow[t] = (m < cnt) ? g_rows[e * CAP + m] : -1;
        sgt[t]  = (m < cnt) ? g_rowg[e * CAP + m] : 0.f;
    }
    __syncthreads();
    int n0 = blockIdx.y * 128;
    const __half* B = g_weffh + (size_t)e * DMODEL * SEQL;

    int lane = t & 31, warp = t >> 5;
    int wm = warp >> 2, wn = warp & 3;
    int lr = lane >> 2, lc = lane & 3;
    int sw = (lr & 6) << 2;

    int offB[4], offA[4];
#pragma unroll
    for (int ni = 0; ni < 4; ni++) offB[ni] = (wn * 32 + ni * 8 + lr) * 32;
#pragma unroll
    for (int mi = 0; mi < 4; mi++) offA[mi] = (wm * 64 + mi * 16 + lr) * 32;

    float acc[4][4][4];
#pragma unroll
    for (int i = 0; i < 4; i++)
#pragma unroll
        for (int j = 0; j < 4; j++)
#pragma unroll
            for (int q = 0; q < 4; q++) acc[i][j][q] = 0.f;

#define LOADE(buf, kt)                                                          \
    {                                                                           \
        _Pragma("unroll")                                                       \
        for (int i = 0; i < 2; i++) {                                           \
            int c = i * 256 + t;                                                \
            int row = c >> 2, ch = c & 3;                                       \
            int off = row * 32 + ((ch * 8) ^ ((row & 6) << 2));                 \
            int gr = srow[row];                                                 \
            int grs = gr < 0 ? 0 : gr;                                          \
            cp16z(&As[buf][off], g_xnh + (size_t)grs * SEQL + (kt) * 32 + ch * 8, gr >= 0); \
            cp16(&Bs[buf][off], B + (size_t)(n0 + row) * SEQL + (kt) * 32 + ch * 8); \
        }                                                                       \
    }

    LOADE(0, 0);
    CP_COMMIT();

    const int KT = SEQL / 32;   // 16
    for (int kt = 0; kt < KT; kt++) {
        int cur = kt & 1;
        if (kt + 1 < KT) {
            LOADE((kt + 1) & 1, kt + 1);
            CP_COMMIT();
            CP_WAIT1();
        } else {
            CP_WAIT0();
        }
        __syncthreads();
        const __half* a_s = As[cur];
        const __half* b_s = Bs[cur];
#pragma unroll
        for (int kb = 0; kb < 32; kb += 16) {
            int k0 = (kb + 2 * lc) ^ sw;
            int k1 = (kb + 2 * lc + 8) ^ sw;
            uint32_t a[4][4], b[4][2];
#pragma unroll
            for (int mi = 0; mi < 4; mi++) {
                a[mi][0] = *(const uint32_t*)&a_s[offA[mi] + k0];
                a[mi][1] = *(const uint32_t*)&a_s[offA[mi] + 256 + k0];
                a[mi][2] = *(const uint32_t*)&a_s[offA[mi] + k1];
                a[mi][3] = *(const uint32_t*)&a_s[offA[mi] + 256 + k1];
            }
#pragma unroll
            for (int ni = 0; ni < 4; ni++) {
                b[ni][0] = *(const uint32_t*)&b_s[offB[ni] + k0];
                b[ni][1] = *(const uint32_t*)&b_s[offB[ni] + k1];
            }
#pragma unroll
            for (int mi = 0; mi < 4; mi++)
#pragma unroll
                for (int ni = 0; ni < 4; ni++)
                    mma16(acc[mi][ni], a[mi], b[ni]);
        }
        __syncthreads();
    }
#undef LOADE

#pragma unroll
    for (int mi = 0; mi < 4; mi++) {
        int ml = wm * 64 + mi * 16 + lr;
        int r0 = srow[ml], r1 = srow[ml + 8];
        float g0 = sgt[ml], g1 = sgt[ml + 8];
#pragma unroll
        for (int ni = 0; ni < 4; ni++) {
            int col = n0 + wn * 32 + ni * 8 + lc * 2;
            if (r0 >= 0)
                redv2(&y[(size_t)r0 * DMODEL + col], g0 * acc[mi][ni][0], g0 * acc[mi][ni][1]);
            if (r1 >= 0)
                redv2(&y[(size_t)r1 * DMODEL + col], g1 * acc[mi][ni][2], g1 * acc[mi][ni][3]);
        }
    }
}

// ---------------- loss ----------------
__global__ void k_loss(const void* lc, float* out, int out_size) {
    float mi = 0.f, ml = 0.f;
#pragma unroll
    for (int e = 0; e < NEXP; e++) { mi += g_imp[e]; ml += g_load[e]; }
    mi *= (1.f / NEXP); ml *= (1.f / NEXP);
    float vi = 0.f, vl = 0.f;
#pragma unroll
    for (int e = 0; e < NEXP; e++) {
        float di = g_imp[e] - mi;  vi += di * di;
        float dl = g_load[e] - ml; vl += dl * dl;
    }
    vi *= (1.f / (NEXP - 1)); vl *= (1.f / (NEXP - 1));
    float cvi = vi / (mi * mi + 1e-10f);
    float cvl = vl / (ml * ml + 1e-10f);
    float coef = 1.f;
    if (lc) {
        int ib = *(const int*)lc;
        float fb = __int_as_float(ib);
        float af = fabsf(fb);
        coef = (af >= 1e-6f && af <= 1e6f) ? fb : (float)ib;
    }
    out[out_size - 1] = (cvi + cvl) * coef;
}

// ---------------- launch ----------------
extern "C" void kernel_launch(void* const* d_in, const int* in_sizes, int n_in,
                              void* d_out, int out_size) {
    const float* x   = (const float*)d_in[0];
    const float* gw1 = (const float*)d_in[1];
    const float* gw2 = (const float*)d_in[2];
    const float* Ws  = (const float*)d_in[3];
    const float* Wt  = (const float*)d_in[4];
    const float* rw  = (const float*)d_in[5];
    const float* rb  = (const float*)d_in[6];
    const void*  lc  = (n_in >= 8) ? d_in[7] : (const void*)0;
    float* out = (float*)d_out;

    k_zero<<<1, 32>>>();
    cudaMemsetAsync(d_out, 0, (size_t)out_size * sizeof(float));
    k_revin<<<NROWS, 128>>>(x, rw, rb);
    k_splitw<<<NW1 / 4 / 256, 256>>>(gw1);
    k_weff<<<NEXP * DMODEL, 128>>>(Ws, Wt);
    k_gemm_h<<<dim3(NROWS / 128, NHID / 128), 256>>>();
    k_gate<<<NROWS / 8, 256>>>(gw2);
    k_lists<<<NROWS / 256, 256>>>();
    k_gemmE<<<dim3(CAP / 128, DMODEL / 128, NEXP), 256>>>(out);
    k_loss<<<1, 1>>>(lc, out, out_size);
}

// round 11
// speedup vs baseline: 1.6911x; 1.0894x over previous
#include <cuda_runtime.h>
#include <cuda_fp16.h>
#include <stdint.h>
#include <math.h>

#define NROWS  14336
#define SEQL   512
#define DMODEL 512
#define NEXP   8
#define NHID   256
#define NVARS  7
#define CAP    NROWS
#define MAVG   25
#define PAD    12
#define NX     (NROWS * SEQL)
#define NW1    (NHID * SEQL)

// ---------------- scratch ----------------
__device__ __half g_xnh [NX];
__device__ float  g_h   [NROWS * NHID];
__device__ __half g_weffh[NEXP * DMODEL * SEQL];
__device__ __half g_xh  [NX];
__device__ __half g_xl  [NX];
__device__ __half g_w1h [NW1];
__device__ __half g_w1l [NW1];
__device__ int    g_tkidx[NROWS * 2];
__device__ float  g_tkg  [NROWS * 2];
__device__ int    g_cnt [NEXP];
__device__ float  g_imp [NEXP];
__device__ float  g_load[NEXP];
__device__ int    g_rows[NEXP * CAP];
__device__ float  g_rowg[NEXP * CAP];

// ---------------- helpers ----------------
__device__ __forceinline__ void cp16(void* dst, const void* src) {
    uint32_t d = (uint32_t)__cvta_generic_to_shared(dst);
    asm volatile("cp.async.cg.shared.global [%0], [%1], 16;\n" :: "r"(d), "l"(src));
}
__device__ __forceinline__ void cp16z(void* dst, const void* src, int pred) {
    uint32_t d = (uint32_t)__cvta_generic_to_shared(dst);
    int bytes = pred ? 16 : 0;
    asm volatile("cp.async.cg.shared.global [%0], [%1], 16, %2;\n"
                 :: "r"(d), "l"(src), "r"(bytes));
}
#define CP_COMMIT() asm volatile("cp.async.commit_group;\n")
#define CP_WAIT0()  asm volatile("cp.async.wait_group 0;\n")
#define CP_WAIT1()  asm volatile("cp.async.wait_group 1;\n")

__device__ __forceinline__ void mma16(float* c, const uint32_t* a, const uint32_t* b) {
    asm volatile(
        "mma.sync.aligned.m16n8k16.row.col.f32.f16.f16.f32 "
        "{%0,%1,%2,%3}, {%4,%5,%6,%7}, {%8,%9}, {%0,%1,%2,%3};"
        : "+f"(c[0]), "+f"(c[1]), "+f"(c[2]), "+f"(c[3])
        : "r"(a[0]), "r"(a[1]), "r"(a[2]), "r"(a[3]), "r"(b[0]), "r"(b[1]));
}
__device__ __forceinline__ void ldsm4(uint32_t& r0, uint32_t& r1, uint32_t& r2,
                                      uint32_t& r3, uint32_t addr) {
    asm volatile("ldmatrix.sync.aligned.m8n8.x4.shared.b16 {%0,%1,%2,%3}, [%4];"
                 : "=r"(r0), "=r"(r1), "=r"(r2), "=r"(r3) : "r"(addr));
}
__device__ __forceinline__ void redv2(float* ptr, float v0, float v1) {
    asm volatile("red.global.add.v2.f32 [%0], {%1, %2};"
                 :: "l"(ptr), "f"(v0), "f"(v1) : "memory");
}

// ---------------- merged prep: zero + revin(+x split) + weff + splitw -------
__global__ void __launch_bounds__(128) k_prep(const float* __restrict__ x,
                                              const float* __restrict__ w1,
                                              const float* __restrict__ Ws,
                                              const float* __restrict__ Wt,
                                              const float* __restrict__ rw,
                                              const float* __restrict__ rb) {
    __shared__ float sh[2][4];
    __shared__ float sW[SEQL];
    __shared__ float sC[SEQL];
    __shared__ float wsum[4];
    int b = blockIdx.x;
    int t = threadIdx.x;

    if (b < NROWS) {
        // ---- RevIN + fused raw-x hi/lo split ----
        int n = b;
        const float* xr = x + (size_t)n * SEQL;
        float v[4];
        float s = 0.f, ss = 0.f;
#pragma unroll
        for (int i = 0; i < 4; i++) {
            v[i] = xr[t + 128 * i];
            s += v[i]; ss += v[i] * v[i];
        }
#pragma unroll
        for (int o = 16; o; o >>= 1) {
            s  += __shfl_xor_sync(0xffffffffu, s, o);
            ss += __shfl_xor_sync(0xffffffffu, ss, o);
        }
        int w = t >> 5;
        if ((t & 31) == 0) { sh[0][w] = s; sh[1][w] = ss; }
        __syncthreads();
        s  = sh[0][0] + sh[0][1] + sh[0][2] + sh[0][3];
        ss = sh[1][0] + sh[1][1] + sh[1][2] + sh[1][3];
        float mean = s * (1.f / SEQL);
        float var  = ss * (1.f / SEQL) - mean * mean;
        float sd   = sqrtf(var + 1e-5f);
        int vv = n % NVARS;
        float sc = rw[vv] / sd;
        float bb = rb[vv];
        size_t base = (size_t)n * SEQL;
#pragma unroll
        for (int i = 0; i < 4; i++) {
            int idx = t + 128 * i;
            g_xnh[base + idx] = __float2half_rn((v[i] - mean) * sc + bb);
            __half hi = __float2half_rn(v[i]);
            g_xh[base + idx] = hi;
            g_xl[base + idx] = __float2half_rn(v[i] - __half2float(hi));
        }
    } else if (b < NROWS + NEXP * DMODEL) {
        // ---- Weff fold via inclusive scan ----
        int ep = b - NROWS;
        int lane = t & 31, w = t >> 5;
        float4 a = ((const float4*)(Ws + (size_t)ep * SEQL))[t];
        float4 bv = ((const float4*)(Wt + (size_t)ep * SEQL))[t];
        float d0 = bv.x - a.x, d1 = bv.y - a.y, d2 = bv.z - a.z, d3 = bv.w - a.w;
        float c0 = d0, c1 = c0 + d1, c2 = c1 + d2, c3 = c2 + d3;
        float pre = c3;
#pragma unroll
        for (int o = 1; o < 32; o <<= 1) {
            float vv2 = __shfl_up_sync(0xffffffffu, pre, o);
            if (lane >= o) pre += vv2;
        }
        if (lane == 31) wsum[w] = pre;
        __syncthreads();
        float base = 0.f;
#pragma unroll
        for (int ww = 0; ww < 4; ww++) if (ww < w) base += wsum[ww];
        float excl = base + pre - c3;
        int j4 = t * 4;
        sC[j4 + 0] = excl + c0;
        sC[j4 + 1] = excl + c1;
        sC[j4 + 2] = excl + c2;
        sC[j4 + 3] = excl + c3;
        sW[j4 + 0] = a.x; sW[j4 + 1] = a.y; sW[j4 + 2] = a.z; sW[j4 + 3] = a.w;
        __syncthreads();
        __half* o = g_weffh + (size_t)ep * SEQL;
#pragma unroll
        for (int i = 0; i < 4; i++) {
            int j = j4 + i;
            float g;
            if (j == 0) {
                g = 0.f;
                for (int k = 0; k <= PAD; k++) g += sC[k];
            } else if (j == SEQL - 1) {
                g = (float)(PAD + 1) * sC[SEQL - 1];
                for (int k = SEQL - 2 - PAD; k < SEQL - 1; k++) g -= sC[k];
            } else {
                int lo = j - PAD; if (lo < 0) lo = 0;
                int hi = j + PAD; if (hi > SEQL - 1) hi = SEQL - 1;
                g = sC[hi] - (lo > 0 ? sC[lo - 1] : 0.f);
            }
            o[j] = __float2half_rn(sW[j] + g * (1.f / MAVG));
        }
    } else if (b < NROWS + NEXP * DMODEL + 256) {
        // ---- split gw1 into fp16 hi/lo ----
        int j = (b - NROWS - NEXP * DMODEL) * 128 + t;   // float4 index, NW1/4
        float4 v = ((const float4*)w1)[j];
        __half h0 = __float2half_rn(v.x), h1 = __float2half_rn(v.y);
        __half h2 = __float2half_rn(v.z), h3 = __float2half_rn(v.w);
        __half l0 = __float2half_rn(v.x - __half2float(h0));
        __half l1 = __float2half_rn(v.y - __half2float(h1));
        __half l2 = __float2half_rn(v.z - __half2float(h2));
        __half l3 = __float2half_rn(v.w - __half2float(h3));
        ((__half2*)g_w1h)[2 * j]     = __halves2half2(h0, h1);
        ((__half2*)g_w1h)[2 * j + 1] = __halves2half2(h2, h3);
        ((__half2*)g_w1l)[2 * j]     = __halves2half2(l0, l1);
        ((__half2*)g_w1l)[2 * j + 1] = __halves2half2(l2, l3);
    } else {
        if (t < NEXP) { g_cnt[t] = 0; g_imp[t] = 0.f; g_load[t] = 0.f; }
    }
}
#define PREP_GRID (NROWS + NEXP * DMODEL + 256 + 1)

// ---------------- GEMM1 (3x fp16 split, ldmatrix): h = relu(x @ gw1^T) ------
__global__ void __launch_bounds__(256, 2) k_gemm_h() {
    __shared__ __half Ah[2][2048], Al[2][2048], Bh[2][2048], Bl[2][2048];
    int m0 = blockIdx.x * 128, n0 = blockIdx.y * 128;
    int t = threadIdx.x;
    int lane = t & 31, warp = t >> 5;
    int wm = warp >> 2, wn = warp & 3;
    int lr = lane >> 2, lc = lane & 3;

    // loader
    int lrow = t >> 1, lch = t & 1;
    int loff = lrow * 16 + ((lch * 8) ^ ((lrow & 4) << 1));
    const __half* pah = g_xh  + (size_t)(m0 + lrow) * SEQL + lch * 8;
    const __half* pal = g_xl  + (size_t)(m0 + lrow) * SEQL + lch * 8;
    const __half* pbh = g_w1h + (size_t)(n0 + lrow) * SEQL + lch * 8;
    const __half* pbl = g_w1l + (size_t)(n0 + lrow) * SEQL + lch * 8;

    // ldmatrix per-lane byte offsets (loop-invariant)
    uint32_t aoff[4], boff[2];
    {
        int rsub = (lane & 7) + ((lane >> 3) & 1) * 8;
        int ck   = (lane >> 4) & 1;          // k-chunk for A
#pragma unroll
        for (int mi = 0; mi < 4; mi++) {
            int row = wm * 64 + mi * 16 + rsub;
            aoff[mi] = (uint32_t)(row * 16 + ((ck * 8) ^ ((row & 4) << 1))) * 2;
        }
        int nin = (lane >> 4) & 1;           // ni within pair
        int cb  = (lane >> 3) & 1;           // k-chunk for B
#pragma unroll
        for (int p = 0; p < 2; p++) {
            int rown = wn * 32 + (p * 2 + nin) * 8 + (lane & 7);
            boff[p] = (uint32_t)(rown * 16 + ((cb * 8) ^ ((rown & 4) << 1))) * 2;
        }
    }
    uint32_t sAh = (uint32_t)__cvta_generic_to_shared(&Ah[0][0]);
    uint32_t sAl = (uint32_t)__cvta_generic_to_shared(&Al[0][0]);
    uint32_t sBh = (uint32_t)__cvta_generic_to_shared(&Bh[0][0]);
    uint32_t sBl = (uint32_t)__cvta_generic_to_shared(&Bl[0][0]);

    float acc[4][4][4];
#pragma unroll
    for (int i = 0; i < 4; i++)
#pragma unroll
        for (int j = 0; j < 4; j++)
#pragma unroll
            for (int q = 0; q < 4; q++) acc[i][j][q] = 0.f;

#define LOADH(buf, kt)                              \
    {                                               \
        cp16(&Ah[buf][loff], pah + (kt) * 16);      \
        cp16(&Al[buf][loff], pal + (kt) * 16);      \
        cp16(&Bh[buf][loff], pbh + (kt) * 16);      \
        cp16(&Bl[buf][loff], pbl + (kt) * 16);      \
    }

    LOADH(0, 0); CP_COMMIT();

    const int KT = SEQL / 16;    // 32
    for (int kt = 0; kt < KT; kt++) {
        int cur = kt & 1;
        if (kt + 1 < KT) {
            LOADH((kt + 1) & 1, kt + 1);
            CP_COMMIT();
            CP_WAIT1();
        } else {
            CP_WAIT0();
        }
        __syncthreads();
        uint32_t bo = (uint32_t)cur * 4096;   // bytes per buffer

        uint32_t bhf[4][2], blf[4][2];
        ldsm4(bhf[0][0], bhf[0][1], bhf[1][0], bhf[1][1], sBh + bo + boff[0]);
        ldsm4(bhf[2][0], bhf[2][1], bhf[3][0], bhf[3][1], sBh + bo + boff[1]);
        ldsm4(blf[0][0], blf[0][1], blf[1][0], blf[1][1], sBl + bo + boff[0]);
        ldsm4(blf[2][0], blf[2][1], blf[3][0], blf[3][1], sBl + bo + boff[1]);
#pragma unroll
        for (int mi = 0; mi < 4; mi++) {
            uint32_t ahf[4], alf[4];
            ldsm4(ahf[0], ahf[1], ahf[2], ahf[3], sAh + bo + aoff[mi]);
            ldsm4(alf[0], alf[1], alf[2], alf[3], sAl + bo + aoff[mi]);
#pragma unroll
            for (int ni = 0; ni < 4; ni++) {
                mma16(acc[mi][ni], ahf, bhf[ni]);
                mma16(acc[mi][ni], alf, bhf[ni]);
                mma16(acc[mi][ni], ahf, blf[ni]);
            }
        }
        __syncthreads();
    }
#undef LOADH

#pragma unroll
    for (int mi = 0; mi < 4; mi++) {
        int row = m0 + wm * 64 + mi * 16 + lr;
#pragma unroll
        for (int ni = 0; ni < 4; ni++) {
            int col = n0 + wn * 32 + ni * 8 + lc * 2;
            float2 v0 = make_float2(fmaxf(acc[mi][ni][0], 0.f), fmaxf(acc[mi][ni][1], 0.f));
            float2 v1 = make_float2(fmaxf(acc[mi][ni][2], 0.f), fmaxf(acc[mi][ni][3], 0.f));
            *(float2*)&g_h[(size_t)row * NHID + col]       = v0;
            *(float2*)&g_h[(size_t)(row + 8) * NHID + col] = v1;
        }
    }
}

// ---------------- gating head ----------------
__global__ void __launch_bounds__(256) k_gate(const float* __restrict__ gw2) {
    __shared__ float sg2[NEXP * NHID];
    int t = threadIdx.x;
    for (int i = t; i < NEXP * NHID; i += 256) sg2[i] = gw2[i];
    __syncthreads();
    int w = t >> 5, lane = t & 31;
    int r = blockIdx.x * 8 + w;
    const float* h = g_h + (size_t)r * NHID;
    float acc[NEXP] = {};
    for (int k = lane; k < NHID; k += 32) {
        float hv = h[k];
#pragma unroll
        for (int e = 0; e < NEXP; e++) acc[e] = fmaf(hv, sg2[e * NHID + k], acc[e]);
    }
#pragma unroll
    for (int e = 0; e < NEXP; e++)
#pragma unroll
        for (int o = 16; o; o >>= 1) acc[e] += __shfl_xor_sync(0xffffffffu, acc[e], o);
    if (lane == 0) {
        float mx = acc[0];
#pragma unroll
        for (int e = 1; e < NEXP; e++) mx = fmaxf(mx, acc[e]);
        float p[NEXP], sum = 0.f;
#pragma unroll
        for (int e = 0; e < NEXP; e++) { p[e] = expf(acc[e] - mx); sum += p[e]; }
        float inv = 1.f / sum;
#pragma unroll
        for (int e = 0; e < NEXP; e++) p[e] *= inv;
        int i1 = 0; float v1 = p[0];
#pragma unroll
        for (int e = 1; e < NEXP; e++) if (p[e] > v1) { v1 = p[e]; i1 = e; }
        int i2 = -1; float v2 = -1.f;
#pragma unroll
        for (int e = 0; e < NEXP; e++)
            if (e != i1 && p[e] > v2) { v2 = p[e]; i2 = e; }
        float den = v1 + v2 + 1e-6f;
        float g1 = v1 / den, g2 = v2 / den;
        g_tkidx[2 * r] = i1; g_tkidx[2 * r + 1] = i2;
        g_tkg[2 * r] = g1;   g_tkg[2 * r + 1] = g2;
        atomicAdd(&g_imp[i1], g1);
        atomicAdd(&g_imp[i2], g2);
        atomicAdd(&g_load[i1], 1.f);
        atomicAdd(&g_load[i2], 1.f);
    }
}

// ---------------- per-expert row lists ----------------
__global__ void __launch_bounds__(256) k_lists() {
    __shared__ int scnt[NEXP], sbase[NEXP];
    int t = threadIdx.x;
    if (t < NEXP) scnt[t] = 0;
    __syncthreads();
    int r = blockIdx.x * 256 + t;
    int i1 = g_tkidx[2 * r], i2 = g_tkidx[2 * r + 1];
    int l1 = atomicAdd(&scnt[i1], 1);
    int l2 = atomicAdd(&scnt[i2], 1);
    __syncthreads();
    if (t < NEXP) sbase[t] = atomicAdd(&g_cnt[t], scnt[t]);
    __syncthreads();
    int p1 = sbase[i1] + l1, p2 = sbase[i2] + l2;
    g_rows[i1 * CAP + p1] = r; g_rowg[i1 * CAP + p1] = g_tkg[2 * r];
    g_rows[i2 * CAP + p2] = r; g_rowg[i2 * CAP + p2] = g_tkg[2 * r + 1];
}

// ---------------- expert GEMM (fp16, ldmatrix) ----------------
__global__ void __launch_bounds__(256, 2) k_gemmE(float* __restrict__ y) {
    int e = blockIdx.z;
    int cnt = g_cnt[e];
    int m0 = blockIdx.x * 128;
    if (m0 >= cnt) return;
    __shared__ __half As[2][4096];
    __shared__ __half Bs[2][4096];
    __shared__ int   srow[128];
    __shared__ float sgt[128];
    int t = threadIdx.x;
    if (t < 128) {
        int m = m0 + t;
        srow[t] = (m < cnt) ? g_rows[e * CAP + m] : -1;
        sgt[t]  = (m < cnt) ? g_rowg[e * CAP + m] : 0.f;
    }
    __syncthreads();
    int n0 = blockIdx.y * 128;
    const __half* B = g_weffh + (size_t)e * DMODEL * SEQL;

    int lane = t & 31, warp = t >> 5;
    int wm = warp >> 2, wn = warp & 3;
    int lr = lane >> 2, lc = lane & 3;

    // ldmatrix per-lane byte offsets (kb=0; kb=16 is addr ^ 32)
    uint32_t aoff[4], boff[2];
    {
        int rsub = (lane & 7) + ((lane >> 3) & 1) * 8;
        int ck   = (lane >> 4) & 1;
#pragma unroll
        for (int mi = 0; mi < 4; mi++) {
            int row = wm * 64 + mi * 16 + rsub;
            aoff[mi] = (uint32_t)(row * 32 + ((ck * 8) ^ ((row & 6) << 2))) * 2;
        }
        int nin = (lane >> 4) & 1;
        int cb  = (lane >> 3) & 1;
#pragma unroll
        for (int p = 0; p < 2; p++) {
            int rown = wn * 32 + (p * 2 + nin) * 8 + (lane & 7);
            boff[p] = (uint32_t)(rown * 32 + ((cb * 8) ^ ((rown & 6) << 2))) * 2;
        }
    }
    uint32_t sA = (uint32_t)__cvta_generic_to_shared(&As[0][0]);
    uint32_t sB = (uint32_t)__cvta_generic_to_shared(&Bs[0][0]);

    float acc[4][4][4];
#pragma unroll
    for (int i = 0; i < 4; i++)
#pragma unroll
        for (int j = 0; j < 4; j++)
#pragma unroll
            for (int q = 0; q < 4; q++) acc[i][j][q] = 0.f;

#define LOADE(buf, kt)                                                          \
    {                                                                           \
        _Pragma("unroll")                                                       \
        for (int i = 0; i < 2; i++) {                                           \
            int c = i * 256 + t;                                                \
            int row = c >> 2, ch = c & 3;                                       \
            int off = row * 32 + ((ch * 8) ^ ((row & 6) << 2));                 \
            int gr = srow[row];                                                 \
            int grs = gr < 0 ? 0 : gr;                                          \
            cp16z(&As[buf][off], g_xnh + (size_t)grs * SEQL + (kt) * 32 + ch * 8, gr >= 0); \
            cp16(&Bs[buf][off], B + (size_t)(n0 + row) * SEQL + (kt) * 32 + ch * 8); \
        }                                                                       \
    }

    LOADE(0, 0);
    CP_COMMIT();

    const int KT = SEQL / 32;   // 16
    for (int kt = 0; kt < KT; kt++) {
        int cur = kt & 1;
        if (kt + 1 < KT) {
            LOADE((kt + 1) & 1, kt + 1);
            CP_COMMIT();
            CP_WAIT1();
        } else {
            CP_WAIT0();
        }
        __syncthreads();
        uint32_t bo = (uint32_t)cur * 8192;   // bytes per buffer
#pragma unroll
        for (int kb = 0; kb < 2; kb++) {
            uint32_t kx = (uint32_t)kb * 32;  // byte XOR for k16 step
            uint32_t bf[4][2];
            ldsm4(bf[0][0], bf[0][1], bf[1][0], bf[1][1], sB + bo + (boff[0] ^ kx));
            ldsm4(bf[2][0], bf[2][1], bf[3][0], bf[3][1], sB + bo + (boff[1] ^ kx));
#pragma unroll
            for (int mi = 0; mi < 4; mi++) {
                uint32_t af[4];
                ldsm4(af[0], af[1], af[2], af[3], sA + bo + (aoff[mi] ^ kx));
#pragma unroll
                for (int ni = 0; ni < 4; ni++)
                    mma16(acc[mi][ni], af, bf[ni]);
            }
        }
        __syncthreads();
    }
#undef LOADE

#pragma unroll
    for (int mi = 0; mi < 4; mi++) {
        int ml = wm * 64 + mi * 16 + lr;
        int r0 = srow[ml], r1 = srow[ml + 8];
        float g0 = sgt[ml], g1 = sgt[ml + 8];
#pragma unroll
        for (int ni = 0; ni < 4; ni++) {
            int col = n0 + wn * 32 + ni * 8 + lc * 2;
            if (r0 >= 0)
                redv2(&y[(size_t)r0 * DMODEL + col], g0 * acc[mi][ni][0], g0 * acc[mi][ni][1]);
            if (r1 >= 0)
                redv2(&y[(size_t)r1 * DMODEL + col], g1 * acc[mi][ni][2], g1 * acc[mi][ni][3]);
        }
    }
}

// ---------------- loss ----------------
__global__ void k_loss(const void* lc, float* out, int out_size) {
    float mi = 0.f, ml = 0.f;
#pragma unroll
    for (int e = 0; e < NEXP; e++) { mi += g_imp[e]; ml += g_load[e]; }
    mi *= (1.f / NEXP); ml *= (1.f / NEXP);
    float vi = 0.f, vl = 0.f;
#pragma unroll
    for (int e = 0; e < NEXP; e++) {
        float di = g_imp[e] - mi;  vi += di * di;
        float dl = g_load[e] - ml; vl += dl * dl;
    }
    vi *= (1.f / (NEXP - 1)); vl *= (1.f / (NEXP - 1));
    float cvi = vi / (mi * mi + 1e-10f);
    float cvl = vl / (ml * ml + 1e-10f);
    float coef = 1.f;
    if (lc) {
        int ib = *(const int*)lc;
        float fb = __int_as_float(ib);
        float af = fabsf(fb);
        coef = (af >= 1e-6f && af <= 1e6f) ? fb : (float)ib;
    }
    out[out_size - 1] = (cvi + cvl) * coef;
}

// ---------------- launch ----------------
extern "C" void kernel_launch(void* const* d_in, const int* in_sizes, int n_in,
                              void* d_out, int out_size) {
    const float* x   = (const float*)d_in[0];
    const float* gw1 = (const float*)d_in[1];
    const float* gw2 = (const float*)d_in[2];
    const float* Ws  = (const float*)d_in[3];
    const float* Wt  = (const float*)d_in[4];
    const float* rw  = (const float*)d_in[5];
    const float* rb  = (const float*)d_in[6];
    const void*  lc  = (n_in >= 8) ? d_in[7] : (const void*)0;
    float* out = (float*)d_out;

    cudaMemsetAsync(d_out, 0, (size_t)out_size * sizeof(float));
    k_prep<<<PREP_GRID, 128>>>(x, gw1, Ws, Wt, rw, rb);
    k_gemm_h<<<dim3(NROWS / 128, NHID / 128), 256>>>();
    k_gate<<<NROWS / 8, 256>>>(gw2);
    k_lists<<<NROWS / 256, 256>>>();
    k_gemmE<<<dim3(CAP / 128, DMODEL / 128, NEXP), 256>>>(out);
    k_loss<<<1, 1>>>(lc, out, out_size);
}

// round 12
// speedup vs baseline: 1.8505x; 1.0943x over previous
#include <cuda_runtime.h>
#include <cuda_fp16.h>
#include <stdint.h>
#include <math.h>

#define NROWS  14336
#define SEQL   512
#define DMODEL 512
#define NEXP   8
#define NHID   256
#define NVARS  7
#define CAP    NROWS
#define MAVG   25
#define PAD    12
#define NX     (NROWS * SEQL)
#define NW1    (NHID * SEQL)

// ---------------- scratch ----------------
__device__ __half g_xnh [NX];
__device__ float  g_h   [NROWS * NHID];
__device__ __half g_weffh[NEXP * DMODEL * SEQL];
__device__ __half g_xh  [NX];
__device__ __half g_xl  [NX];
__device__ __half g_w1h [NW1];
__device__ __half g_w1l [NW1];
__device__ int    g_cnt0[NEXP];
__device__ int    g_cnt1[NEXP];
__device__ float  g_imp [NEXP];
__device__ float  g_load[NEXP];
__device__ int    g_rows0[NEXP * CAP];
__device__ float  g_rowg0[NEXP * CAP];
__device__ int    g_rows1[NEXP * CAP];
__device__ float  g_rowg1[NEXP * CAP];

// ---------------- helpers ----------------
__device__ __forceinline__ void cp16(void* dst, const void* src) {
    uint32_t d = (uint32_t)__cvta_generic_to_shared(dst);
    asm volatile("cp.async.cg.shared.global [%0], [%1], 16;\n" :: "r"(d), "l"(src));
}
__device__ __forceinline__ void cp16z(void* dst, const void* src, int pred) {
    uint32_t d = (uint32_t)__cvta_generic_to_shared(dst);
    int bytes = pred ? 16 : 0;
    asm volatile("cp.async.cg.shared.global [%0], [%1], 16, %2;\n"
                 :: "r"(d), "l"(src), "r"(bytes));
}
#define CP_COMMIT() asm volatile("cp.async.commit_group;\n")
#define CP_WAIT0()  asm volatile("cp.async.wait_group 0;\n")
#define CP_WAIT1()  asm volatile("cp.async.wait_group 1;\n")

__device__ __forceinline__ void mma16(float* c, const uint32_t* a, const uint32_t* b) {
    asm volatile(
        "mma.sync.aligned.m16n8k16.row.col.f32.f16.f16.f32 "
        "{%0,%1,%2,%3}, {%4,%5,%6,%7}, {%8,%9}, {%0,%1,%2,%3};"
        : "+f"(c[0]), "+f"(c[1]), "+f"(c[2]), "+f"(c[3])
        : "r"(a[0]), "r"(a[1]), "r"(a[2]), "r"(a[3]), "r"(b[0]), "r"(b[1]));
}
__device__ __forceinline__ void ldsm4(uint32_t& r0, uint32_t& r1, uint32_t& r2,
                                      uint32_t& r3, uint32_t addr) {
    asm volatile("ldmatrix.sync.aligned.m8n8.x4.shared.b16 {%0,%1,%2,%3}, [%4];"
                 : "=r"(r0), "=r"(r1), "=r"(r2), "=r"(r3) : "r"(addr));
}
__device__ __forceinline__ void redv2(float* ptr, float v0, float v1) {
    asm volatile("red.global.add.v2.f32 [%0], {%1, %2};"
                 :: "l"(ptr), "f"(v0), "f"(v1) : "memory");
}

// ---------------- merged prep: zero + revin(+x split) + weff + splitw -------
__global__ void __launch_bounds__(128) k_prep(const float* __restrict__ x,
                                              const float* __restrict__ w1,
                                              const float* __restrict__ Ws,
                                              const float* __restrict__ Wt,
                                              const float* __restrict__ rw,
                                              const float* __restrict__ rb) {
    __shared__ float sh[2][4];
    __shared__ float sW[SEQL];
    __shared__ float sC[SEQL];
    __shared__ float wsum[4];
    int b = blockIdx.x;
    int t = threadIdx.x;

    if (b < NROWS) {
        int n = b;
        const float* xr = x + (size_t)n * SEQL;
        float v[4];
        float s = 0.f, ss = 0.f;
#pragma unroll
        for (int i = 0; i < 4; i++) {
            v[i] = xr[t + 128 * i];
            s += v[i]; ss += v[i] * v[i];
        }
#pragma unroll
        for (int o = 16; o; o >>= 1) {
            s  += __shfl_xor_sync(0xffffffffu, s, o);
            ss += __shfl_xor_sync(0xffffffffu, ss, o);
        }
        int w = t >> 5;
        if ((t & 31) == 0) { sh[0][w] = s; sh[1][w] = ss; }
        __syncthreads();
        s  = sh[0][0] + sh[0][1] + sh[0][2] + sh[0][3];
        ss = sh[1][0] + sh[1][1] + sh[1][2] + sh[1][3];
        float mean = s * (1.f / SEQL);
        float var  = ss * (1.f / SEQL) - mean * mean;
        float sd   = sqrtf(var + 1e-5f);
        int vv = n % NVARS;
        float sc = rw[vv] / sd;
        float bb = rb[vv];
        size_t base = (size_t)n * SEQL;
#pragma unroll
        for (int i = 0; i < 4; i++) {
            int idx = t + 128 * i;
            g_xnh[base + idx] = __float2half_rn((v[i] - mean) * sc + bb);
            __half hi = __float2half_rn(v[i]);
            g_xh[base + idx] = hi;
            g_xl[base + idx] = __float2half_rn(v[i] - __half2float(hi));
        }
    } else if (b < NROWS + NEXP * DMODEL) {
        int ep = b - NROWS;
        int lane = t & 31, w = t >> 5;
        float4 a = ((const float4*)(Ws + (size_t)ep * SEQL))[t];
        float4 bv = ((const float4*)(Wt + (size_t)ep * SEQL))[t];
        float d0 = bv.x - a.x, d1 = bv.y - a.y, d2 = bv.z - a.z, d3 = bv.w - a.w;
        float c0 = d0, c1 = c0 + d1, c2 = c1 + d2, c3 = c2 + d3;
        float pre = c3;
#pragma unroll
        for (int o = 1; o < 32; o <<= 1) {
            float vv2 = __shfl_up_sync(0xffffffffu, pre, o);
            if (lane >= o) pre += vv2;
        }
        if (lane == 31) wsum[w] = pre;
        __syncthreads();
        float base = 0.f;
#pragma unroll
        for (int ww = 0; ww < 4; ww++) if (ww < w) base += wsum[ww];
        float excl = base + pre - c3;
        int j4 = t * 4;
        sC[j4 + 0] = excl + c0;
        sC[j4 + 1] = excl + c1;
        sC[j4 + 2] = excl + c2;
        sC[j4 + 3] = excl + c3;
        sW[j4 + 0] = a.x; sW[j4 + 1] = a.y; sW[j4 + 2] = a.z; sW[j4 + 3] = a.w;
        __syncthreads();
        __half* o = g_weffh + (size_t)ep * SEQL;
#pragma unroll
        for (int i = 0; i < 4; i++) {
            int j = j4 + i;
            float g;
            if (j == 0) {
                g = 0.f;
                for (int k = 0; k <= PAD; k++) g += sC[k];
            } else if (j == SEQL - 1) {
                g = (float)(PAD + 1) * sC[SEQL - 1];
                for (int k = SEQL - 2 - PAD; k < SEQL - 1; k++) g -= sC[k];
            } else {
                int lo = j - PAD; if (lo < 0) lo = 0;
                int hi = j + PAD; if (hi > SEQL - 1) hi = SEQL - 1;
                g = sC[hi] - (lo > 0 ? sC[lo - 1] : 0.f);
            }
            o[j] = __float2half_rn(sW[j] + g * (1.f / MAVG));
        }
    } else if (b < NROWS + NEXP * DMODEL + 256) {
        int j = (b - NROWS - NEXP * DMODEL) * 128 + t;
        float4 v = ((const float4*)w1)[j];
        __half h0 = __float2half_rn(v.x), h1 = __float2half_rn(v.y);
        __half h2 = __float2half_rn(v.z), h3 = __float2half_rn(v.w);
        __half l0 = __float2half_rn(v.x - __half2float(h0));
        __half l1 = __float2half_rn(v.y - __half2float(h1));
        __half l2 = __float2half_rn(v.z - __half2float(h2));
        __half l3 = __float2half_rn(v.w - __half2float(h3));
        ((__half2*)g_w1h)[2 * j]     = __halves2half2(h0, h1);
        ((__half2*)g_w1h)[2 * j + 1] = __halves2half2(h2, h3);
        ((__half2*)g_w1l)[2 * j]     = __halves2half2(l0, l1);
        ((__half2*)g_w1l)[2 * j + 1] = __halves2half2(l2, l3);
    } else {
        if (t < NEXP) {
            g_cnt0[t] = 0; g_cnt1[t] = 0;
            g_imp[t] = 0.f; g_load[t] = 0.f;
        }
    }
}
#define PREP_GRID (NROWS + NEXP * DMODEL + 256 + 1)

// ---------------- GEMM1 (3x fp16 split, ldmatrix): h = relu(x @ gw1^T) ------
__global__ void __launch_bounds__(256, 2) k_gemm_h() {
    __shared__ __half Ah[2][2048], Al[2][2048], Bh[2][2048], Bl[2][2048];
    int m0 = blockIdx.x * 128, n0 = blockIdx.y * 128;
    int t = threadIdx.x;
    int lane = t & 31, warp = t >> 5;
    int wm = warp >> 2, wn = warp & 3;
    int lr = lane >> 2, lc = lane & 3;

    int lrow = t >> 1, lch = t & 1;
    int loff = lrow * 16 + ((lch * 8) ^ ((lrow & 4) << 1));
    const __half* pah = g_xh  + (size_t)(m0 + lrow) * SEQL + lch * 8;
    const __half* pal = g_xl  + (size_t)(m0 + lrow) * SEQL + lch * 8;
    const __half* pbh = g_w1h + (size_t)(n0 + lrow) * SEQL + lch * 8;
    const __half* pbl = g_w1l + (size_t)(n0 + lrow) * SEQL + lch * 8;

    uint32_t aoff[4], boff[2];
    {
        int rsub = (lane & 7) + ((lane >> 3) & 1) * 8;
        int ck   = (lane >> 4) & 1;
#pragma unroll
        for (int mi = 0; mi < 4; mi++) {
            int row = wm * 64 + mi * 16 + rsub;
            aoff[mi] = (uint32_t)(row * 16 + ((ck * 8) ^ ((row & 4) << 1))) * 2;
        }
        int nin = (lane >> 4) & 1;
        int cb  = (lane >> 3) & 1;
#pragma unroll
        for (int p = 0; p < 2; p++) {
            int rown = wn * 32 + (p * 2 + nin) * 8 + (lane & 7);
            boff[p] = (uint32_t)(rown * 16 + ((cb * 8) ^ ((rown & 4) << 1))) * 2;
        }
    }
    uint32_t sAh = (uint32_t)__cvta_generic_to_shared(&Ah[0][0]);
    uint32_t sAl = (uint32_t)__cvta_generic_to_shared(&Al[0][0]);
    uint32_t sBh = (uint32_t)__cvta_generic_to_shared(&Bh[0][0]);
    uint32_t sBl = (uint32_t)__cvta_generic_to_shared(&Bl[0][0]);

    float acc[4][4][4];
#pragma unroll
    for (int i = 0; i < 4; i++)
#pragma unroll
        for (int j = 0; j < 4; j++)
#pragma unroll
            for (int q = 0; q < 4; q++) acc[i][j][q] = 0.f;

#define LOADH(buf, kt)                              \
    {                                               \
        cp16(&Ah[buf][loff], pah + (kt) * 16);      \
        cp16(&Al[buf][loff], pal + (kt) * 16);      \
        cp16(&Bh[buf][loff], pbh + (kt) * 16);      \
        cp16(&Bl[buf][loff], pbl + (kt) * 16);      \
    }

    LOADH(0, 0); CP_COMMIT();

    const int KT = SEQL / 16;
    for (int kt = 0; kt < KT; kt++) {
        int cur = kt & 1;
        if (kt + 1 < KT) {
            LOADH((kt + 1) & 1, kt + 1);
            CP_COMMIT();
            CP_WAIT1();
        } else {
            CP_WAIT0();
        }
        __syncthreads();
        uint32_t bo = (uint32_t)cur * 4096;

        uint32_t bhf[4][2], blf[4][2];
        ldsm4(bhf[0][0], bhf[0][1], bhf[1][0], bhf[1][1], sBh + bo + boff[0]);
        ldsm4(bhf[2][0], bhf[2][1], bhf[3][0], bhf[3][1], sBh + bo + boff[1]);
        ldsm4(blf[0][0], blf[0][1], blf[1][0], blf[1][1], sBl + bo + boff[0]);
        ldsm4(blf[2][0], blf[2][1], blf[3][0], blf[3][1], sBl + bo + boff[1]);
#pragma unroll
        for (int mi = 0; mi < 4; mi++) {
            uint32_t ahf[4], alf[4];
            ldsm4(ahf[0], ahf[1], ahf[2], ahf[3], sAh + bo + aoff[mi]);
            ldsm4(alf[0], alf[1], alf[2], alf[3], sAl + bo + aoff[mi]);
#pragma unroll
            for (int ni = 0; ni < 4; ni++) {
                mma16(acc[mi][ni], ahf, bhf[ni]);
                mma16(acc[mi][ni], alf, bhf[ni]);
                mma16(acc[mi][ni], ahf, blf[ni]);
            }
        }
        __syncthreads();
    }
#undef LOADH

#pragma unroll
    for (int mi = 0; mi < 4; mi++) {
        int row = m0 + wm * 64 + mi * 16 + lr;
#pragma unroll
        for (int ni = 0; ni < 4; ni++) {
            int col = n0 + wn * 32 + ni * 8 + lc * 2;
            float2 v0 = make_float2(fmaxf(acc[mi][ni][0], 0.f), fmaxf(acc[mi][ni][1], 0.f));
            float2 v1 = make_float2(fmaxf(acc[mi][ni][2], 0.f), fmaxf(acc[mi][ni][3], 0.f));
            *(float2*)&g_h[(size_t)row * NHID + col]       = v0;
            *(float2*)&g_h[(size_t)(row + 8) * NHID + col] = v1;
        }
    }
}

// ---------------- fused gating head + list build ----------------
// 56 blocks x 1024 threads; each warp computes 8 rows; block-aggregated
// counters (same atomic profile as old k_lists) then scatter into
// first-choice (list0) and second-choice (list1) expert lists.
__global__ void __launch_bounds__(1024) k_gate(const float* __restrict__ gw2) {
    __shared__ float sg2[NEXP * NHID];
    __shared__ int   s_i1[256], s_i2[256], s_p1[256], s_p2[256];
    __shared__ float s_g1[256], s_g2[256];
    __shared__ int   scnt0[NEXP], scnt1[NEXP], sbase0[NEXP], sbase1[NEXP];
    __shared__ float simp[NEXP], sload[NEXP];
    int t = threadIdx.x;
    if (t < NEXP) { scnt0[t] = 0; scnt1[t] = 0; simp[t] = 0.f; sload[t] = 0.f; }
    for (int i = t; i < NEXP * NHID; i += 1024) sg2[i] = gw2[i];
    __syncthreads();
    int w = t >> 5, lane = t & 31;
#pragma unroll
    for (int j = 0; j < 8; j++) {
        int li = w * 8 + j;
        int r = blockIdx.x * 256 + li;
        const float* h = g_h + (size_t)r * NHID;
        float acc[NEXP] = {};
        for (int k = lane; k < NHID; k += 32) {
            float hv = h[k];
#pragma unroll
            for (int e = 0; e < NEXP; e++) acc[e] = fmaf(hv, sg2[e * NHID + k], acc[e]);
        }
#pragma unroll
        for (int e = 0; e < NEXP; e++)
#pragma unroll
            for (int o = 16; o; o >>= 1) acc[e] += __shfl_xor_sync(0xffffffffu, acc[e], o);
        if (lane == 0) {
            float mx = acc[0];
#pragma unroll
            for (int e = 1; e < NEXP; e++) mx = fmaxf(mx, acc[e]);
            float p[NEXP], sum = 0.f;
#pragma unroll
            for (int e = 0; e < NEXP; e++) { p[e] = expf(acc[e] - mx); sum += p[e]; }
            float inv = 1.f / sum;
#pragma unroll
            for (int e = 0; e < NEXP; e++) p[e] *= inv;
            int i1 = 0; float v1 = p[0];
#pragma unroll
            for (int e = 1; e < NEXP; e++) if (p[e] > v1) { v1 = p[e]; i1 = e; }
            int i2 = -1; float v2 = -1.f;
#pragma unroll
            for (int e = 0; e < NEXP; e++)
                if (e != i1 && p[e] > v2) { v2 = p[e]; i2 = e; }
            float den = v1 + v2 + 1e-6f;
            float g1 = v1 / den, g2 = v2 / den;
            s_i1[li] = i1; s_i2[li] = i2; s_g1[li] = g1; s_g2[li] = g2;
            s_p1[li] = atomicAdd(&scnt0[i1], 1);
            s_p2[li] = atomicAdd(&scnt1[i2], 1);
            atomicAdd(&simp[i1], g1);
            atomicAdd(&simp[i2], g2);
            atomicAdd(&sload[i1], 1.f);
            atomicAdd(&sload[i2], 1.f);
        }
    }
    __syncthreads();
    if (t < NEXP) {
        sbase0[t] = atomicAdd(&g_cnt0[t], scnt0[t]);
        sbase1[t] = atomicAdd(&g_cnt1[t], scnt1[t]);
        atomicAdd(&g_imp[t], simp[t]);
        atomicAdd(&g_load[t], sload[t]);
    }
    __syncthreads();
    if (t < 256) {
        int r = blockIdx.x * 256 + t;
        int i1 = s_i1[t], i2 = s_i2[t];
        int p1 = sbase0[i1] + s_p1[t];
        int p2 = sbase1[i2] + s_p2[t];
        g_rows0[i1 * CAP + p1] = r; g_rowg0[i1 * CAP + p1] = s_g1[t];
        g_rows1[i2 * CAP + p2] = r; g_rowg1[i2 * CAP + p2] = s_g2[t];
    }
}

// ---------------- expert GEMM (fp16, ldmatrix), two phases ------------------
// PHASE 0: first-choice list, plain STG (covers every row exactly once).
// PHASE 1: second-choice list, red accumulate.
template <int PHASE>
__global__ void __launch_bounds__(256, 2) k_gemmE(float* __restrict__ y) {
    int e = blockIdx.z;
    const int*   grows = PHASE ? g_rows1 : g_rows0;
    const float* growg = PHASE ? g_rowg1 : g_rowg0;
    int cnt = PHASE ? g_cnt1[e] : g_cnt0[e];
    int m0 = blockIdx.x * 128;
    if (m0 >= cnt) return;
    __shared__ __half As[2][4096];
    __shared__ __half Bs[2][4096];
    __shared__ int   srow[128];
    __shared__ float sgt[128];
    int t = threadIdx.x;
    if (t < 128) {
        int m = m0 + t;
        srow[t] = (m < cnt) ? grows[e * CAP + m] : -1;
        sgt[t]  = (m < cnt) ? growg[e * CAP + m] : 0.f;
    }
    __syncthreads();
    int n0 = blockIdx.y * 128;
    const __half* B = g_weffh + (size_t)e * DMODEL * SEQL;

    int lane = t & 31, warp = t >> 5;
    int wm = warp >> 2, wn = warp & 3;
    int lr = lane >> 2, lc = lane & 3;

    uint32_t aoff[4], boff[2];
    {
        int rsub = (lane & 7) + ((lane >> 3) & 1) * 8;
        int ck   = (lane >> 4) & 1;
#pragma unroll
        for (int mi = 0; mi < 4; mi++) {
            int row = wm * 64 + mi * 16 + rsub;
            aoff[mi] = (uint32_t)(row * 32 + ((ck * 8) ^ ((row & 6) << 2))) * 2;
        }
        int nin = (lane >> 4) & 1;
        int cb  = (lane >> 3) & 1;
#pragma unroll
        for (int p = 0; p < 2; p++) {
            int rown = wn * 32 + (p * 2 + nin) * 8 + (lane & 7);
            boff[p] = (uint32_t)(rown * 32 + ((cb * 8) ^ ((rown & 6) << 2))) * 2;
        }
    }
    uint32_t sA = (uint32_t)__cvta_generic_to_shared(&As[0][0]);
    uint32_t sB = (uint32_t)__cvta_generic_to_shared(&Bs[0][0]);

    float acc[4][4][4];
#pragma unroll
    for (int i = 0; i < 4; i++)
#pragma unroll
        for (int j = 0; j < 4; j++)
#pragma unroll
            for (int q = 0; q < 4; q++) acc[i][j][q] = 0.f;

#define LOADE(buf, kt)                                                          \
    {                                                                           \
        _Pragma("unroll")                                                       \
        for (int i = 0; i < 2; i++) {                                           \
            int c = i * 256 + t;                                                \
            int row = c >> 2, ch = c & 3;                                       \
            int off = row * 32 + ((ch * 8) ^ ((row & 6) << 2));                 \
            int gr = srow[row];                                                 \
            int grs = gr < 0 ? 0 : gr;                                          \
            cp16z(&As[buf][off], g_xnh + (size_t)grs * SEQL + (kt) * 32 + ch * 8, gr >= 0); \
            cp16(&Bs[buf][off], B + (size_t)(n0 + row) * SEQL + (kt) * 32 + ch * 8); \
        }                                                                       \
    }

    LOADE(0, 0);
    CP_COMMIT();

    const int KT = SEQL / 32;
    for (int kt = 0; kt < KT; kt++) {
        int cur = kt & 1;
        if (kt + 1 < KT) {
            LOADE((kt + 1) & 1, kt + 1);
            CP_COMMIT();
            CP_WAIT1();
        } else {
            CP_WAIT0();
        }
        __syncthreads();
        uint32_t bo = (uint32_t)cur * 8192;
#pragma unroll
        for (int kb = 0; kb < 2; kb++) {
            uint32_t kx = (uint32_t)kb * 32;
            uint32_t bf[4][2];
            ldsm4(bf[0][0], bf[0][1], bf[1][0], bf[1][1], sB + bo + (boff[0] ^ kx));
            ldsm4(bf[2][0], bf[2][1], bf[3][0], bf[3][1], sB + bo + (boff[1] ^ kx));
#pragma unroll
            for (int mi = 0; mi < 4; mi++) {
                uint32_t af[4];
                ldsm4(af[0], af[1], af[2], af[3], sA + bo + (aoff[mi] ^ kx));
#pragma unroll
                for (int ni = 0; ni < 4; ni++)
                    mma16(acc[mi][ni], af, bf[ni]);
            }
        }
        __syncthreads();
    }
#undef LOADE

#pragma unroll
    for (int mi = 0; mi < 4; mi++) {
        int ml = wm * 64 + mi * 16 + lr;
        int r0 = srow[ml], r1 = srow[ml + 8];
        float g0 = sgt[ml], g1 = sgt[ml + 8];
#pragma unroll
        for (int ni = 0; ni < 4; ni++) {
            int col = n0 + wn * 32 + ni * 8 + lc * 2;
            if (PHASE == 0) {
                if (r0 >= 0)
                    *(float2*)&y[(size_t)r0 * DMODEL + col] =
                        make_float2(g0 * acc[mi][ni][0], g0 * acc[mi][ni][1]);
                if (r1 >= 0)
                    *(float2*)&y[(size_t)r1 * DMODEL + col] =
                        make_float2(g1 * acc[mi][ni][2], g1 * acc[mi][ni][3]);
            } else {
                if (r0 >= 0)
                    redv2(&y[(size_t)r0 * DMODEL + col], g0 * acc[mi][ni][0], g0 * acc[mi][ni][1]);
                if (r1 >= 0)
                    redv2(&y[(size_t)r1 * DMODEL + col], g1 * acc[mi][ni][2], g1 * acc[mi][ni][3]);
            }
        }
    }
}

// ---------------- loss ----------------
__global__ void k_loss(const void* lc, float* out, int out_size) {
    float mi = 0.f, ml = 0.f;
#pragma unroll
    for (int e = 0; e < NEXP; e++) { mi += g_imp[e]; ml += g_load[e]; }
    mi *= (1.f / NEXP); ml *= (1.f / NEXP);
    float vi = 0.f, vl = 0.f;
#pragma unroll
    for (int e = 0; e < NEXP; e++) {
        float di = g_imp[e] - mi;  vi += di * di;
        float dl = g_load[e] - ml; vl += dl * dl;
    }
    vi *= (1.f / (NEXP - 1)); vl *= (1.f / (NEXP - 1));
    float cvi = vi / (mi * mi + 1e-10f);
    float cvl = vl / (ml * ml + 1e-10f);
    float coef = 1.f;
    if (lc) {
        int ib = *(const int*)lc;
        float fb = __int_as_float(ib);
        float af = fabsf(fb);
        coef = (af >= 1e-6f && af <= 1e6f) ? fb : (float)ib;
    }
    out[out_size - 1] = (cvi + cvl) * coef;
}

// ---------------- launch ----------------
extern "C" void kernel_launch(void* const* d_in, const int* in_sizes, int n_in,
                              void* d_out, int out_size) {
    const float* x   = (const float*)d_in[0];
    const float* gw1 = (const float*)d_in[1];
    const float* gw2 = (const float*)d_in[2];
    const float* Ws  = (const float*)d_in[3];
    const float* Wt  = (const float*)d_in[4];
    const float* rw  = (const float*)d_in[5];
    const float* rb  = (const float*)d_in[6];
    const void*  lc  = (n_in >= 8) ? d_in[7] : (const void*)0;
    float* out = (float*)d_out;

    cudaMemsetAsync(d_out, 0, (size_t)out_size * sizeof(float));
    k_prep<<<PREP_GRID, 128>>>(x, gw1, Ws, Wt, rw, rb);
    k_gemm_h<<<dim3(NROWS / 128, NHID / 128), 256>>>();
    k_gate<<<NROWS / 256, 1024>>>(gw2);
    k_gemmE<0><<<dim3(CAP / 128, DMODEL / 128, NEXP), 256>>>(out);
    k_gemmE<1><<<dim3(CAP / 128, DMODEL / 128, NEXP), 256>>>(out);
    k_loss<<<1, 1>>>(lc, out, out_size);
}